// round 1
// baseline (speedup 1.0000x reference)
#include <cuda_runtime.h>
#include <cuda_bf16.h>
#include <cstddef>
#include <cstdint>

// Problem constants
// B=16, N=512, D=256, H=8, DH=32, E=16384
// d_out layout (floats):
//   attended_img   [0,        2097152)
//   attended_text  [2097152,  4194304)
//   cross_modal    [4194304,  6291456)
//   img_weights    [6291456, 10485760)
//   text_weights   [10485760,14680064)
//   img_cons       [14680064,14688256)
//   text_cons      [14688256,14696448)

// Scratch layout (floats)
#define OFF_WCAT   0u             // 256*1280
#define OFF_BIAS1  327680u        // 1280
#define OFF_WOT    328960u        // 256*256
#define OFF_PROJ   394496u        // 16384*1280  (also reused as H for consistency)
#define OFF_CTX    21366016u      // 16384*256
#define OFF_QC     25560320u      // 8192*256
#define OFF_KVC    27657472u      // 8192*512
#define OFF_CTX2   31851776u      // 8192*256
#define SCRATCH_FLOATS 33948928u

__device__ float g_scratch[SCRATCH_FLOATS];

// ---------------------------------------------------------------------------
// Pack: wcat[k][c] (256 x 1280), bias1[1280], wot = out_w^T (256x256)
// cols: [0,256)=w1_top  [256,512)=w1_bot  [512,768)=wq^T [768,1024)=wk^T [1024,1280)=wv^T
// bias1: [0,256)=b1, [256,512)=0, [512,1280)=in_b
// ---------------------------------------------------------------------------
__global__ void pack_kernel(const float* __restrict__ w1, const float* __restrict__ b1,
                            const float* __restrict__ in_w, const float* __restrict__ in_b,
                            const float* __restrict__ out_w,
                            float* __restrict__ wcat, float* __restrict__ bias1,
                            float* __restrict__ wot)
{
    int idx = blockIdx.x * 256 + threadIdx.x;
    if (idx < 327680) {
        int k = idx / 1280, c = idx % 1280;
        float v;
        if (c < 256)       v = w1[k * 256 + c];
        else if (c < 512)  v = w1[(256 + k) * 256 + (c - 256)];
        else if (c < 768)  v = in_w[(c - 512) * 256 + k];
        else if (c < 1024) v = in_w[(c - 768 + 256) * 256 + k];
        else               v = in_w[(c - 1024 + 512) * 256 + k];
        wcat[idx] = v;
    } else if (idx < 328960) {
        int c = idx - 327680;
        float v = (c < 256) ? b1[c] : (c < 512 ? 0.0f : in_b[c - 512]);
        bias1[c] = v;
    } else if (idx < 394496) {
        int i = idx - 328960;
        int k = i / 256, n = i % 256;
        wot[i] = out_w[n * 256 + k];
    }
}

// ---------------------------------------------------------------------------
// Generic fp32 GEMM:  C[M x Nc] = X[M x 256] * W[256 x Nc] (+bias) (opt relu)
// K is fixed at 256. Tiles 64x64x16, 256 threads, 4x4 per thread.
// grid.x = M/64, grid.y = Nc/64.
// ---------------------------------------------------------------------------
__global__ void gemm64(const float* __restrict__ X, int ldx,
                       const float* __restrict__ W, int ldw, int woff,
                       const float* __restrict__ bias, int boff,
                       float* __restrict__ C, int ldc,
                       int relu)
{
    __shared__ __align__(16) float As[16][65];
    __shared__ __align__(16) float Bs[16][64];

    int t  = threadIdx.x;
    int tx = t & 15, ty = t >> 4;
    int m0 = blockIdx.x * 64, n0 = blockIdx.y * 64;

    float acc[4][4];
    #pragma unroll
    for (int i = 0; i < 4; i++)
        #pragma unroll
        for (int j = 0; j < 4; j++) acc[i][j] = 0.0f;

    int lr = t >> 2;            // 0..63 : X row within tile
    int lk = (t & 3) * 4;       // k offset within chunk
    int wk = t >> 4;            // 0..15 : W k-row within chunk
    int wn = (t & 15) * 4;      // n offset within tile

    for (int k0 = 0; k0 < 256; k0 += 16) {
        float4 xa = *(const float4*)(X + (size_t)(m0 + lr) * ldx + k0 + lk);
        As[lk + 0][lr] = xa.x;
        As[lk + 1][lr] = xa.y;
        As[lk + 2][lr] = xa.z;
        As[lk + 3][lr] = xa.w;
        float4 wb = *(const float4*)(W + (size_t)(k0 + wk) * ldw + woff + n0 + wn);
        *(float4*)&Bs[wk][wn] = wb;
        __syncthreads();
        #pragma unroll
        for (int k = 0; k < 16; k++) {
            float a0 = As[k][ty * 4 + 0];
            float a1 = As[k][ty * 4 + 1];
            float a2 = As[k][ty * 4 + 2];
            float a3 = As[k][ty * 4 + 3];
            float4 b4 = *(const float4*)&Bs[k][tx * 4];
            acc[0][0] += a0 * b4.x; acc[0][1] += a0 * b4.y; acc[0][2] += a0 * b4.z; acc[0][3] += a0 * b4.w;
            acc[1][0] += a1 * b4.x; acc[1][1] += a1 * b4.y; acc[1][2] += a1 * b4.z; acc[1][3] += a1 * b4.w;
            acc[2][0] += a2 * b4.x; acc[2][1] += a2 * b4.y; acc[2][2] += a2 * b4.z; acc[2][3] += a2 * b4.w;
            acc[3][0] += a3 * b4.x; acc[3][1] += a3 * b4.y; acc[3][2] += a3 * b4.z; acc[3][3] += a3 * b4.w;
        }
        __syncthreads();
    }

    int n = n0 + tx * 4;
    float bb0 = bias ? bias[boff + n + 0] : 0.0f;
    float bb1 = bias ? bias[boff + n + 1] : 0.0f;
    float bb2 = bias ? bias[boff + n + 2] : 0.0f;
    float bb3 = bias ? bias[boff + n + 3] : 0.0f;
    #pragma unroll
    for (int i = 0; i < 4; i++) {
        float4 o;
        o.x = acc[i][0] + bb0;
        o.y = acc[i][1] + bb1;
        o.z = acc[i][2] + bb2;
        o.w = acc[i][3] + bb3;
        if (relu) {
            o.x = fmaxf(o.x, 0.0f); o.y = fmaxf(o.y, 0.0f);
            o.z = fmaxf(o.z, 0.0f); o.w = fmaxf(o.w, 0.0f);
        }
        *(float4*)(C + (size_t)(m0 + ty * 4 + i) * ldc + n) = o;
    }
}

// ---------------------------------------------------------------------------
// Edge scatter: one warp per (modality, batch, edge).
// h = relu(A[src] + Bm[dst])  (b1 already folded into A's bias)
// v = sigmoid(h . w2 + b2) -> weights[m][b][src][dst]
// proj rows stride 1280: A at col 0, Bm at col 256.
// ---------------------------------------------------------------------------
__global__ void edge_kernel(const float* __restrict__ proj,
                            const int* __restrict__ src, const int* __restrict__ dst,
                            const float* __restrict__ w2, const float* __restrict__ b2p,
                            float* __restrict__ wout)
{
    int gw   = (blockIdx.x * blockDim.x + threadIdx.x) >> 5;
    int lane = threadIdx.x & 31;
    int e = gw & 16383;
    int b = (gw >> 14) & 15;
    int m = gw >> 18;
    int s = src[e], d = dst[e];

    const float4* ar = (const float4*)(proj + ((size_t)m * 8192 + b * 512 + s) * 1280);
    const float4* br = (const float4*)(proj + ((size_t)m * 8192 + b * 512 + d) * 1280 + 256);
    const float4* w4 = (const float4*)w2;

    float p = 0.0f;
    #pragma unroll
    for (int u = 0; u < 2; u++) {
        int idx = u * 32 + lane;
        float4 a = ar[idx], bb = br[idx], w = w4[idx];
        p += fmaxf(a.x + bb.x, 0.0f) * w.x;
        p += fmaxf(a.y + bb.y, 0.0f) * w.y;
        p += fmaxf(a.z + bb.z, 0.0f) * w.z;
        p += fmaxf(a.w + bb.w, 0.0f) * w.w;
    }
    #pragma unroll
    for (int off = 16; off > 0; off >>= 1)
        p += __shfl_xor_sync(0xFFFFFFFFu, p, off);
    if (lane == 0) {
        float v = 1.0f / (1.0f + __expf(-(p + b2p[0])));
        wout[(size_t)m * 4194304 + (size_t)b * 262144 + (size_t)s * 512 + d] = v;
    }
}

// ---------------------------------------------------------------------------
// Attention core (pre out-proj). Block = (chunk of 128 rows, head, batch).
// 256 threads = 8 warps; each warp does 16 rows, 2 at a time (amortizes smem).
// K/V for this (b,h) staged in smem, stride-33 padded. Full-row softmax
// (N=512 -> 16 scores/lane in registers). Optional additive mask [B,N,N].
// ---------------------------------------------------------------------------
__global__ void attn_kernel(const float* __restrict__ qbuf, int qld, int qoff,
                            const float* __restrict__ kbuf, int kld, int koff,
                            const float* __restrict__ vbuf, int vld, int voff,
                            const float* __restrict__ mask,
                            float* __restrict__ ctx)
{
    extern __shared__ float sm[];
    float* Ks  = sm;              // 512*33
    float* Vs  = sm + 16896;      // 512*33
    float* red = sm + 33792;      // 8 * 32*33

    int b = blockIdx.z, h = blockIdx.y, chunk = blockIdx.x;
    int t = threadIdx.x, lane = t & 31, w = t >> 5;

    for (int idx = t; idx < 16384; idx += 256) {
        int j = idx >> 5, d = idx & 31;
        size_t rowk = (size_t)(b * 512 + j);
        Ks[j * 33 + d] = kbuf[rowk * kld + koff + h * 32 + d];
        Vs[j * 33 + d] = vbuf[rowk * vld + voff + h * 32 + d];
    }
    __syncthreads();

    float* myred = red + w * 1056;
    const float scale = 0.17677669529663687f;  // 1/sqrt(32)

    for (int rr = 0; rr < 8; rr++) {
        int i0 = chunk * 128 + w * 16 + rr * 2;
        const float* q0p = qbuf + (size_t)(b * 512 + i0) * qld + qoff + h * 32;
        const float* q1p = q0p + qld;
        float q0[32], q1[32];
        #pragma unroll
        for (int d = 0; d < 32; d++) { q0[d] = q0p[d]; q1[d] = q1p[d]; }

        float s0[16], s1[16];
        #pragma unroll
        for (int jt = 0; jt < 16; jt++) {
            int j = jt * 32 + lane;
            const float* kr = Ks + j * 33;
            float a0 = 0.0f, a1 = 0.0f;
            #pragma unroll
            for (int d = 0; d < 32; d++) {
                float kk = kr[d];
                a0 += q0[d] * kk;
                a1 += q1[d] * kk;
            }
            a0 *= scale; a1 *= scale;
            if (mask) {
                a0 += mask[(size_t)b * 262144 + (size_t)i0 * 512 + j];
                a1 += mask[(size_t)b * 262144 + (size_t)(i0 + 1) * 512 + j];
            }
            s0[jt] = a0; s1[jt] = a1;
        }

        float m0 = -1e30f, m1 = -1e30f;
        #pragma unroll
        for (int jt = 0; jt < 16; jt++) { m0 = fmaxf(m0, s0[jt]); m1 = fmaxf(m1, s1[jt]); }
        #pragma unroll
        for (int off = 16; off > 0; off >>= 1) {
            m0 = fmaxf(m0, __shfl_xor_sync(0xFFFFFFFFu, m0, off));
            m1 = fmaxf(m1, __shfl_xor_sync(0xFFFFFFFFu, m1, off));
        }
        float l0 = 0.0f, l1 = 0.0f;
        #pragma unroll
        for (int jt = 0; jt < 16; jt++) {
            float p0 = __expf(s0[jt] - m0); s0[jt] = p0; l0 += p0;
            float p1 = __expf(s1[jt] - m1); s1[jt] = p1; l1 += p1;
        }
        #pragma unroll
        for (int off = 16; off > 0; off >>= 1) {
            l0 += __shfl_xor_sync(0xFFFFFFFFu, l0, off);
            l1 += __shfl_xor_sync(0xFFFFFFFFu, l1, off);
        }

        float o0[32], o1[32];
        #pragma unroll
        for (int d = 0; d < 32; d++) { o0[d] = 0.0f; o1[d] = 0.0f; }
        #pragma unroll
        for (int jt = 0; jt < 16; jt++) {
            int j = jt * 32 + lane;
            const float* vr = Vs + j * 33;
            float p0 = s0[jt], p1 = s1[jt];
            #pragma unroll
            for (int d = 0; d < 32; d++) {
                float vv = vr[d];
                o0[d] += p0 * vv;
                o1[d] += p1 * vv;
            }
        }

        float inv0 = 1.0f / l0, inv1 = 1.0f / l1;

        #pragma unroll
        for (int d = 0; d < 32; d++) myred[lane * 33 + d] = o0[d];
        __syncwarp();
        float r0 = 0.0f;
        #pragma unroll
        for (int jj = 0; jj < 32; jj++) r0 += myred[jj * 33 + lane];
        __syncwarp();
        #pragma unroll
        for (int d = 0; d < 32; d++) myred[lane * 33 + d] = o1[d];
        __syncwarp();
        float r1 = 0.0f;
        #pragma unroll
        for (int jj = 0; jj < 32; jj++) r1 += myred[jj * 33 + lane];
        __syncwarp();

        ctx[(size_t)(b * 512 + i0)     * 256 + h * 32 + lane] = r0 * inv0;
        ctx[(size_t)(b * 512 + i0 + 1) * 256 + h * 32 + lane] = r1 * inv1;
    }
}

// ---------------------------------------------------------------------------
// Consistency reduce: one warp per row. c = sigmoid(H[row] . cw2 + cb2)
// ---------------------------------------------------------------------------
__global__ void cons_reduce(const float* __restrict__ H, const float* __restrict__ cw2,
                            const float* __restrict__ cb2, float* __restrict__ out)
{
    int gw   = (blockIdx.x * blockDim.x + threadIdx.x) >> 5;  // row 0..16383
    int lane = threadIdx.x & 31;
    const float4* h4 = (const float4*)(H + (size_t)gw * 256);
    const float4* w4 = (const float4*)cw2;
    float p = 0.0f;
    #pragma unroll
    for (int u = 0; u < 2; u++) {
        int idx = u * 32 + lane;
        float4 a = h4[idx], w = w4[idx];
        p += a.x * w.x + a.y * w.y + a.z * w.z + a.w * w.w;
    }
    #pragma unroll
    for (int off = 16; off > 0; off >>= 1)
        p += __shfl_xor_sync(0xFFFFFFFFu, p, off);
    if (lane == 0)
        out[gw] = 1.0f / (1.0f + __expf(-(p + cb2[0])));
}

// ---------------------------------------------------------------------------
extern "C" void kernel_launch(void* const* d_in, const int* in_sizes, int n_in,
                              void* d_out, int out_size)
{
    const float* img   = (const float*)d_in[0];
    const float* txt   = (const float*)d_in[1];
    const int*   src   = (const int*)  d_in[2];
    const int*   dst   = (const int*)  d_in[3];
    const float* w1    = (const float*)d_in[4];
    const float* b1    = (const float*)d_in[5];
    const float* w2    = (const float*)d_in[6];
    const float* b2    = (const float*)d_in[7];
    const float* in_w  = (const float*)d_in[8];
    const float* in_b  = (const float*)d_in[9];
    const float* out_w = (const float*)d_in[10];
    const float* out_b = (const float*)d_in[11];
    const float* cw1   = (const float*)d_in[12];
    const float* cb1   = (const float*)d_in[13];
    const float* cw2   = (const float*)d_in[14];
    const float* cb2   = (const float*)d_in[15];
    float* out = (float*)d_out;

    float* S = nullptr;
    cudaGetSymbolAddress((void**)&S, g_scratch);

    float* wcat  = S + OFF_WCAT;
    float* bias1 = S + OFF_BIAS1;
    float* wot   = S + OFF_WOT;
    float* proj  = S + OFF_PROJ;
    float* ctx   = S + OFF_CTX;
    float* qc    = S + OFF_QC;
    float* kvc   = S + OFF_KVC;
    float* ctx2  = S + OFF_CTX2;
    float* Hbuf  = proj;  // reuse after attention consumes proj

    float* att_img = out;
    float* att_txt = out + 2097152;
    float* cross   = out + 4194304;
    float* wimg    = out + 6291456;
    float* cons    = out + 14680064;

    const int ATTN_SMEM = (16896 + 16896 + 8448) * 4;  // 168960 B
    cudaFuncSetAttribute(attn_kernel, cudaFuncAttributeMaxDynamicSharedMemorySize, ATTN_SMEM);

    // 1. pack fused weights
    pack_kernel<<<1541, 256>>>(w1, b1, in_w, in_b, out_w, wcat, bias1, wot);

    // 2. zero both weight matrices (img + text adjacent, 8388608 floats)
    cudaMemsetAsync(wimg, 0, (size_t)8388608 * 4);

    // 3. fused node projections: A|Bm|Q|K|V per modality
    gemm64<<<dim3(128, 20), 256>>>(img, 256, wcat, 1280, 0, bias1, 0, proj, 1280, 0);
    gemm64<<<dim3(128, 20), 256>>>(txt, 256, wcat, 1280, 0, bias1, 0,
                                   proj + (size_t)8192 * 1280, 1280, 0);

    // 4. per-edge causal weights (both modalities)
    edge_kernel<<<65536, 256>>>(proj, src, dst, w2, b2, wimg);

    // 5. masked self-attention (img, text) -> ctx (pre out-proj)
    attn_kernel<<<dim3(4, 8, 16), 256, ATTN_SMEM>>>(
        proj, 1280, 512, proj, 1280, 768, proj, 1280, 1024, wimg, ctx);
    attn_kernel<<<dim3(4, 8, 16), 256, ATTN_SMEM>>>(
        proj + (size_t)8192 * 1280, 1280, 512,
        proj + (size_t)8192 * 1280, 1280, 768,
        proj + (size_t)8192 * 1280, 1280, 1024,
        wimg + 4194304, ctx + (size_t)8192 * 256);

    // 6. out-proj for both modalities at once (rows contiguous) -> attended_*
    gemm64<<<dim3(256, 4), 256>>>(ctx, 256, wot, 256, 0, out_b, 0, att_img, 256, 0);

    // 7. consistency: H = relu(attended @ cw1 + cb1); c = sigmoid(H.cw2 + cb2)
    gemm64<<<dim3(256, 4), 256>>>(att_img, 256, cw1, 256, 0, cb1, 0, Hbuf, 256, 1);
    cons_reduce<<<2048, 256>>>(Hbuf, cw2, cb2, cons);

    // 8. cross-modal: Qc from attended_img, K/V from attended_text (reuse wcat cols)
    gemm64<<<dim3(128, 4), 256>>>(att_img, 256, wcat, 1280, 512, bias1, 512, qc, 256, 0);
    gemm64<<<dim3(128, 8), 256>>>(att_txt, 256, wcat, 1280, 768, bias1, 768, kvc, 512, 0);
    attn_kernel<<<dim3(4, 8, 16), 256, ATTN_SMEM>>>(
        qc, 256, 0, kvc, 512, 0, kvc, 512, 256, nullptr, ctx2);
    gemm64<<<dim3(128, 4), 256>>>(ctx2, 256, wot, 256, 0, out_b, 0, cross, 256, 0);
}

// round 2
// speedup vs baseline: 1.3670x; 1.3670x over previous
#include <cuda_runtime.h>
#include <cuda_bf16.h>
#include <cstddef>
#include <cstdint>

// Problem constants: B=16, N=512, D=256, H=8, DH=32, E=16384
// d_out layout (floats):
//   attended_img   [0,        2097152)
//   attended_text  [2097152,  4194304)
//   cross_modal    [4194304,  6291456)
//   img_weights    [6291456, 10485760)
//   text_weights   [10485760,14680064)
//   img_cons       [14680064,14688256)
//   text_cons      [14688256,14696448)

#define OFF_WCAT   0u             // 256*1280
#define OFF_BIAS1  327680u        // 1280
#define OFF_WOT    328960u        // 256*256
#define OFF_PROJ   394496u        // 16384*1280  (reused as H for consistency)
#define OFF_CTX    21366016u      // 16384*256
#define OFF_QC     25560320u      // 8192*256
#define OFF_KVC    27657472u      // 8192*512
#define OFF_CTX2   31851776u      // 8192*256
#define SCRATCH_FLOATS 33948928u

__device__ float g_scratch[SCRATCH_FLOATS];

// ---------------------------------------------------------------------------
__device__ __forceinline__ uint32_t f2tf32(float f) {
    uint32_t r;
    asm("cvt.rna.tf32.f32 %0, %1;" : "=r"(r) : "f"(f));
    return r;
}

__device__ __forceinline__ void mma_tf32(float& d0, float& d1, float& d2, float& d3,
                                         uint32_t a0, uint32_t a1, uint32_t a2, uint32_t a3,
                                         uint32_t b0, uint32_t b1)
{
    asm volatile(
        "mma.sync.aligned.m16n8k8.row.col.f32.tf32.tf32.f32 "
        "{%0,%1,%2,%3}, {%4,%5,%6,%7}, {%8,%9}, {%0,%1,%2,%3};"
        : "+f"(d0), "+f"(d1), "+f"(d2), "+f"(d3)
        : "r"(a0), "r"(a1), "r"(a2), "r"(a3), "r"(b0), "r"(b1));
}

// ---------------------------------------------------------------------------
// Pack: wcat[k][c] (256 x 1280), bias1[1280], wot = out_w^T (256x256)
// cols: [0,256)=w1_top [256,512)=w1_bot [512,768)=wq^T [768,1024)=wk^T [1024,1280)=wv^T
// bias1: [0,256)=b1, [256,512)=0, [512,1280)=in_b
// ---------------------------------------------------------------------------
__global__ void pack_kernel(const float* __restrict__ w1, const float* __restrict__ b1,
                            const float* __restrict__ in_w, const float* __restrict__ in_b,
                            const float* __restrict__ out_w,
                            float* __restrict__ wcat, float* __restrict__ bias1,
                            float* __restrict__ wot)
{
    int idx = blockIdx.x * 256 + threadIdx.x;
    if (idx < 327680) {
        int k = idx / 1280, c = idx % 1280;
        float v;
        if (c < 256)       v = w1[k * 256 + c];
        else if (c < 512)  v = w1[(256 + k) * 256 + (c - 256)];
        else if (c < 768)  v = in_w[(c - 512) * 256 + k];
        else if (c < 1024) v = in_w[(c - 768 + 256) * 256 + k];
        else               v = in_w[(c - 1024 + 512) * 256 + k];
        wcat[idx] = v;
    } else if (idx < 328960) {
        int c = idx - 327680;
        float v = (c < 256) ? b1[c] : (c < 512 ? 0.0f : in_b[c - 512]);
        bias1[c] = v;
    } else if (idx < 394496) {
        int i = idx - 328960;
        int k = i / 256, n = i % 256;
        wot[i] = out_w[n * 256 + k];
    }
}

// ---------------------------------------------------------------------------
// Tensor-core tf32 GEMM: C[M x Nc] = X[M x 256] * W[256 x Nc] (+bias)(opt relu)
// Block tile 128x128, K fixed 256, K-chunk 32. 256 threads = 8 warps (2x4),
// each warp 64x32 via 4x4 m16n8k8 mma tiles. Conflict-free smem padding.
// grid = (M/128, Nc/128).
// ---------------------------------------------------------------------------
__global__ void gemm_tc(const float* __restrict__ X, int ldx,
                        const float* __restrict__ W, int ldw, int woff,
                        const float* __restrict__ bias, int boff,
                        float* __restrict__ C, int ldc, int relu)
{
    __shared__ uint32_t As[128][36];   // row-major, stride 36 (conflict-free)
    __shared__ uint32_t Bs[32][136];   // k-major,  stride 136 (conflict-free)

    int t = threadIdx.x;
    int lane = t & 31, w = t >> 5;
    int gid = lane >> 2, tig = lane & 3;
    int wm = w >> 2, wn = w & 3;        // warp grid 2 x 4
    int m0 = blockIdx.x * 128, n0 = blockIdx.y * 128;

    float acc[4][4][4];
    #pragma unroll
    for (int mi = 0; mi < 4; mi++)
        #pragma unroll
        for (int ni = 0; ni < 4; ni++)
            #pragma unroll
            for (int q = 0; q < 4; q++) acc[mi][ni][q] = 0.0f;

    for (int k0 = 0; k0 < 256; k0 += 32) {
        // Stage A tile 128x32 (4096 floats, 4 x float4 per thread)
        #pragma unroll
        for (int i = 0; i < 4; i++) {
            int lin = i * 1024 + t * 4;
            int r = lin >> 5, c = lin & 31;
            float4 v = *(const float4*)(X + (size_t)(m0 + r) * ldx + k0 + c);
            As[r][c + 0] = f2tf32(v.x);
            As[r][c + 1] = f2tf32(v.y);
            As[r][c + 2] = f2tf32(v.z);
            As[r][c + 3] = f2tf32(v.w);
        }
        // Stage B tile 32x128
        #pragma unroll
        for (int i = 0; i < 4; i++) {
            int lin = i * 1024 + t * 4;
            int r = lin >> 7, c = lin & 127;
            float4 v = *(const float4*)(W + (size_t)(k0 + r) * ldw + woff + n0 + c);
            Bs[r][c + 0] = f2tf32(v.x);
            Bs[r][c + 1] = f2tf32(v.y);
            Bs[r][c + 2] = f2tf32(v.z);
            Bs[r][c + 3] = f2tf32(v.w);
        }
        __syncthreads();

        #pragma unroll
        for (int ks = 0; ks < 4; ks++) {
            int kk = ks * 8;
            uint32_t a[4][4], b[4][2];
            #pragma unroll
            for (int mi = 0; mi < 4; mi++) {
                int rb = wm * 64 + mi * 16 + gid;
                a[mi][0] = As[rb][kk + tig];
                a[mi][1] = As[rb + 8][kk + tig];
                a[mi][2] = As[rb][kk + tig + 4];
                a[mi][3] = As[rb + 8][kk + tig + 4];
            }
            #pragma unroll
            for (int ni = 0; ni < 4; ni++) {
                int cb = wn * 32 + ni * 8 + gid;
                b[ni][0] = Bs[kk + tig][cb];
                b[ni][1] = Bs[kk + tig + 4][cb];
            }
            #pragma unroll
            for (int mi = 0; mi < 4; mi++)
                #pragma unroll
                for (int ni = 0; ni < 4; ni++)
                    mma_tf32(acc[mi][ni][0], acc[mi][ni][1], acc[mi][ni][2], acc[mi][ni][3],
                             a[mi][0], a[mi][1], a[mi][2], a[mi][3],
                             b[ni][0], b[ni][1]);
        }
        __syncthreads();
    }

    // Epilogue
    #pragma unroll
    for (int mi = 0; mi < 4; mi++) {
        int r0 = m0 + wm * 64 + mi * 16 + gid;
        #pragma unroll
        for (int ni = 0; ni < 4; ni++) {
            int col = n0 + wn * 32 + ni * 8 + 2 * tig;
            float bb0 = bias ? bias[boff + col]     : 0.0f;
            float bb1 = bias ? bias[boff + col + 1] : 0.0f;
            float2 v0, v1;
            v0.x = acc[mi][ni][0] + bb0; v0.y = acc[mi][ni][1] + bb1;
            v1.x = acc[mi][ni][2] + bb0; v1.y = acc[mi][ni][3] + bb1;
            if (relu) {
                v0.x = fmaxf(v0.x, 0.0f); v0.y = fmaxf(v0.y, 0.0f);
                v1.x = fmaxf(v1.x, 0.0f); v1.y = fmaxf(v1.y, 0.0f);
            }
            *(float2*)(C + (size_t)r0 * ldc + col)       = v0;
            *(float2*)(C + (size_t)(r0 + 8) * ldc + col) = v1;
        }
    }
}

// ---------------------------------------------------------------------------
// Edge scatter: one warp per (modality, batch, edge).
// ---------------------------------------------------------------------------
__global__ void edge_kernel(const float* __restrict__ proj,
                            const int* __restrict__ src, const int* __restrict__ dst,
                            const float* __restrict__ w2, const float* __restrict__ b2p,
                            float* __restrict__ wout)
{
    int gw   = (blockIdx.x * blockDim.x + threadIdx.x) >> 5;
    int lane = threadIdx.x & 31;
    int e = gw & 16383;
    int b = (gw >> 14) & 15;
    int m = gw >> 18;
    int s = src[e], d = dst[e];

    const float4* ar = (const float4*)(proj + ((size_t)m * 8192 + b * 512 + s) * 1280);
    const float4* br = (const float4*)(proj + ((size_t)m * 8192 + b * 512 + d) * 1280 + 256);
    const float4* w4 = (const float4*)w2;

    float p = 0.0f;
    #pragma unroll
    for (int u = 0; u < 2; u++) {
        int idx = u * 32 + lane;
        float4 a = ar[idx], bb = br[idx], w = w4[idx];
        p += fmaxf(a.x + bb.x, 0.0f) * w.x;
        p += fmaxf(a.y + bb.y, 0.0f) * w.y;
        p += fmaxf(a.z + bb.z, 0.0f) * w.z;
        p += fmaxf(a.w + bb.w, 0.0f) * w.w;
    }
    #pragma unroll
    for (int off = 16; off > 0; off >>= 1)
        p += __shfl_xor_sync(0xFFFFFFFFu, p, off);
    if (lane == 0) {
        float v = 1.0f / (1.0f + __expf(-(p + b2p[0])));
        wout[(size_t)m * 4194304 + (size_t)b * 262144 + (size_t)s * 512 + d] = v;
    }
}

// ---------------------------------------------------------------------------
// Attention core (pre out-proj). Block = (chunk of 128 rows, head, batch).
// ---------------------------------------------------------------------------
__global__ void attn_kernel(const float* __restrict__ qbuf, int qld, int qoff,
                            const float* __restrict__ kbuf, int kld, int koff,
                            const float* __restrict__ vbuf, int vld, int voff,
                            const float* __restrict__ mask,
                            float* __restrict__ ctx)
{
    extern __shared__ float sm[];
    float* Ks  = sm;              // 512*33
    float* Vs  = sm + 16896;      // 512*33
    float* red = sm + 33792;      // 8 * 32*33

    int b = blockIdx.z, h = blockIdx.y, chunk = blockIdx.x;
    int t = threadIdx.x, lane = t & 31, w = t >> 5;

    for (int idx = t; idx < 16384; idx += 256) {
        int j = idx >> 5, d = idx & 31;
        size_t rowk = (size_t)(b * 512 + j);
        Ks[j * 33 + d] = kbuf[rowk * kld + koff + h * 32 + d];
        Vs[j * 33 + d] = vbuf[rowk * vld + voff + h * 32 + d];
    }
    __syncthreads();

    float* myred = red + w * 1056;
    const float scale = 0.17677669529663687f;  // 1/sqrt(32)

    for (int rr = 0; rr < 8; rr++) {
        int i0 = chunk * 128 + w * 16 + rr * 2;
        const float* q0p = qbuf + (size_t)(b * 512 + i0) * qld + qoff + h * 32;
        const float* q1p = q0p + qld;
        float q0[32], q1[32];
        #pragma unroll
        for (int d = 0; d < 32; d++) { q0[d] = q0p[d]; q1[d] = q1p[d]; }

        float s0[16], s1[16];
        #pragma unroll
        for (int jt = 0; jt < 16; jt++) {
            int j = jt * 32 + lane;
            const float* kr = Ks + j * 33;
            float a0 = 0.0f, a1 = 0.0f;
            #pragma unroll
            for (int d = 0; d < 32; d++) {
                float kk = kr[d];
                a0 += q0[d] * kk;
                a1 += q1[d] * kk;
            }
            a0 *= scale; a1 *= scale;
            if (mask) {
                a0 += mask[(size_t)b * 262144 + (size_t)i0 * 512 + j];
                a1 += mask[(size_t)b * 262144 + (size_t)(i0 + 1) * 512 + j];
            }
            s0[jt] = a0; s1[jt] = a1;
        }

        float m0 = -1e30f, m1 = -1e30f;
        #pragma unroll
        for (int jt = 0; jt < 16; jt++) { m0 = fmaxf(m0, s0[jt]); m1 = fmaxf(m1, s1[jt]); }
        #pragma unroll
        for (int off = 16; off > 0; off >>= 1) {
            m0 = fmaxf(m0, __shfl_xor_sync(0xFFFFFFFFu, m0, off));
            m1 = fmaxf(m1, __shfl_xor_sync(0xFFFFFFFFu, m1, off));
        }
        float l0 = 0.0f, l1 = 0.0f;
        #pragma unroll
        for (int jt = 0; jt < 16; jt++) {
            float p0 = __expf(s0[jt] - m0); s0[jt] = p0; l0 += p0;
            float p1 = __expf(s1[jt] - m1); s1[jt] = p1; l1 += p1;
        }
        #pragma unroll
        for (int off = 16; off > 0; off >>= 1) {
            l0 += __shfl_xor_sync(0xFFFFFFFFu, l0, off);
            l1 += __shfl_xor_sync(0xFFFFFFFFu, l1, off);
        }

        float o0[32], o1[32];
        #pragma unroll
        for (int d = 0; d < 32; d++) { o0[d] = 0.0f; o1[d] = 0.0f; }
        #pragma unroll
        for (int jt = 0; jt < 16; jt++) {
            int j = jt * 32 + lane;
            const float* vr = Vs + j * 33;
            float p0 = s0[jt], p1 = s1[jt];
            #pragma unroll
            for (int d = 0; d < 32; d++) {
                float vv = vr[d];
                o0[d] += p0 * vv;
                o1[d] += p1 * vv;
            }
        }

        float inv0 = 1.0f / l0, inv1 = 1.0f / l1;

        #pragma unroll
        for (int d = 0; d < 32; d++) myred[lane * 33 + d] = o0[d];
        __syncwarp();
        float r0 = 0.0f;
        #pragma unroll
        for (int jj = 0; jj < 32; jj++) r0 += myred[jj * 33 + lane];
        __syncwarp();
        #pragma unroll
        for (int d = 0; d < 32; d++) myred[lane * 33 + d] = o1[d];
        __syncwarp();
        float r1 = 0.0f;
        #pragma unroll
        for (int jj = 0; jj < 32; jj++) r1 += myred[jj * 33 + lane];
        __syncwarp();

        ctx[(size_t)(b * 512 + i0)     * 256 + h * 32 + lane] = r0 * inv0;
        ctx[(size_t)(b * 512 + i0 + 1) * 256 + h * 32 + lane] = r1 * inv1;
    }
}

// ---------------------------------------------------------------------------
__global__ void cons_reduce(const float* __restrict__ H, const float* __restrict__ cw2,
                            const float* __restrict__ cb2, float* __restrict__ out)
{
    int gw   = (blockIdx.x * blockDim.x + threadIdx.x) >> 5;  // row 0..16383
    int lane = threadIdx.x & 31;
    const float4* h4 = (const float4*)(H + (size_t)gw * 256);
    const float4* w4 = (const float4*)cw2;
    float p = 0.0f;
    #pragma unroll
    for (int u = 0; u < 2; u++) {
        int idx = u * 32 + lane;
        float4 a = h4[idx], w = w4[idx];
        p += a.x * w.x + a.y * w.y + a.z * w.z + a.w * w.w;
    }
    #pragma unroll
    for (int off = 16; off > 0; off >>= 1)
        p += __shfl_xor_sync(0xFFFFFFFFu, p, off);
    if (lane == 0)
        out[gw] = 1.0f / (1.0f + __expf(-(p + cb2[0])));
}

// ---------------------------------------------------------------------------
extern "C" void kernel_launch(void* const* d_in, const int* in_sizes, int n_in,
                              void* d_out, int out_size)
{
    const float* img   = (const float*)d_in[0];
    const float* txt   = (const float*)d_in[1];
    const int*   src   = (const int*)  d_in[2];
    const int*   dst   = (const int*)  d_in[3];
    const float* w1    = (const float*)d_in[4];
    const float* b1    = (const float*)d_in[5];
    const float* w2    = (const float*)d_in[6];
    const float* b2    = (const float*)d_in[7];
    const float* in_w  = (const float*)d_in[8];
    const float* in_b  = (const float*)d_in[9];
    const float* out_w = (const float*)d_in[10];
    const float* out_b = (const float*)d_in[11];
    const float* cw1   = (const float*)d_in[12];
    const float* cb1   = (const float*)d_in[13];
    const float* cw2   = (const float*)d_in[14];
    const float* cb2   = (const float*)d_in[15];
    float* out = (float*)d_out;

    float* S = nullptr;
    cudaGetSymbolAddress((void**)&S, g_scratch);

    float* wcat  = S + OFF_WCAT;
    float* bias1 = S + OFF_BIAS1;
    float* wot   = S + OFF_WOT;
    float* proj  = S + OFF_PROJ;
    float* ctx   = S + OFF_CTX;
    float* qc    = S + OFF_QC;
    float* kvc   = S + OFF_KVC;
    float* ctx2  = S + OFF_CTX2;
    float* Hbuf  = proj;  // reuse after attention consumes proj

    float* att_img = out;
    float* att_txt = out + 2097152;
    float* cross   = out + 4194304;
    float* wimg    = out + 6291456;
    float* cons    = out + 14680064;

    const int ATTN_SMEM = (16896 + 16896 + 8448) * 4;  // 168960 B
    cudaFuncSetAttribute(attn_kernel, cudaFuncAttributeMaxDynamicSharedMemorySize, ATTN_SMEM);

    // 1. pack fused weights
    pack_kernel<<<1541, 256>>>(w1, b1, in_w, in_b, out_w, wcat, bias1, wot);

    // 2. zero both weight matrices (img + text adjacent, 8388608 floats)
    cudaMemsetAsync(wimg, 0, (size_t)8388608 * 4);

    // 3. fused node projections: A|Bm|Q|K|V per modality (tf32 tensor cores)
    gemm_tc<<<dim3(64, 10), 256>>>(img, 256, wcat, 1280, 0, bias1, 0, proj, 1280, 0);
    gemm_tc<<<dim3(64, 10), 256>>>(txt, 256, wcat, 1280, 0, bias1, 0,
                                   proj + (size_t)8192 * 1280, 1280, 0);

    // 4. per-edge causal weights (both modalities)
    edge_kernel<<<65536, 256>>>(proj, src, dst, w2, b2, wimg);

    // 5. masked self-attention (img, text) -> ctx (pre out-proj)
    attn_kernel<<<dim3(4, 8, 16), 256, ATTN_SMEM>>>(
        proj, 1280, 512, proj, 1280, 768, proj, 1280, 1024, wimg, ctx);
    attn_kernel<<<dim3(4, 8, 16), 256, ATTN_SMEM>>>(
        proj + (size_t)8192 * 1280, 1280, 512,
        proj + (size_t)8192 * 1280, 1280, 768,
        proj + (size_t)8192 * 1280, 1280, 1024,
        wimg + 4194304, ctx + (size_t)8192 * 256);

    // 6. out-proj for both modalities at once -> attended_*
    gemm_tc<<<dim3(128, 2), 256>>>(ctx, 256, wot, 256, 0, out_b, 0, att_img, 256, 0);

    // 7. consistency: H = relu(attended @ cw1 + cb1); c = sigmoid(H.cw2 + cb2)
    gemm_tc<<<dim3(128, 2), 256>>>(att_img, 256, cw1, 256, 0, cb1, 0, Hbuf, 256, 1);
    cons_reduce<<<2048, 256>>>(Hbuf, cw2, cb2, cons);

    // 8. cross-modal: Qc from attended_img, K/V from attended_text
    gemm_tc<<<dim3(64, 2), 256>>>(att_img, 256, wcat, 1280, 512, bias1, 512, qc, 256, 0);
    gemm_tc<<<dim3(64, 4), 256>>>(att_txt, 256, wcat, 1280, 768, bias1, 768, kvc, 512, 0);
    attn_kernel<<<dim3(4, 8, 16), 256, ATTN_SMEM>>>(
        qc, 256, 0, kvc, 512, 0, kvc, 512, 256, nullptr, ctx2);
    gemm_tc<<<dim3(64, 2), 256>>>(ctx2, 256, wot, 256, 0, out_b, 0, cross, 256, 0);
}

// round 3
// speedup vs baseline: 1.9950x; 1.4594x over previous
#include <cuda_runtime.h>
#include <cuda_bf16.h>
#include <cstddef>
#include <cstdint>

// Problem constants: B=16, N=512, D=256, H=8, DH=32, E=16384
// d_out layout (floats):
//   attended_img   [0,        2097152)
//   attended_text  [2097152,  4194304)
//   cross_modal    [4194304,  6291456)
//   img_weights    [6291456, 10485760)
//   text_weights   [10485760,14680064)
//   img_cons       [14680064,14688256)
//   text_cons      [14688256,14696448)

#define OFF_WCAT   0u             // 256*1280
#define OFF_BIAS1  327680u        // 1280
#define OFF_WOT    328960u        // 256*256
#define OFF_PROJ   394496u        // 16384*1280  (reused as H for consistency)
#define OFF_CTX    21366016u      // 16384*256
#define OFF_QC     25560320u      // 8192*256
#define OFF_KVC    27657472u      // 8192*512
#define OFF_CTX2   31851776u      // 8192*256
#define SCRATCH_FLOATS 33948928u

__device__ float g_scratch[SCRATCH_FLOATS];

// ---------------------------------------------------------------------------
__device__ __forceinline__ uint32_t f2tf32(float f) {
    uint32_t r;
    asm("cvt.rna.tf32.f32 %0, %1;" : "=r"(r) : "f"(f));
    return r;
}

__device__ __forceinline__ void mma_tf32(float& d0, float& d1, float& d2, float& d3,
                                         uint32_t a0, uint32_t a1, uint32_t a2, uint32_t a3,
                                         uint32_t b0, uint32_t b1)
{
    asm volatile(
        "mma.sync.aligned.m16n8k8.row.col.f32.tf32.tf32.f32 "
        "{%0,%1,%2,%3}, {%4,%5,%6,%7}, {%8,%9}, {%0,%1,%2,%3};"
        : "+f"(d0), "+f"(d1), "+f"(d2), "+f"(d3)
        : "r"(a0), "r"(a1), "r"(a2), "r"(a3), "r"(b0), "r"(b1));
}

// ---------------------------------------------------------------------------
// Pack: wcat[k][c] (256 x 1280), bias1[1280], wot = out_w^T (256x256)
// cols: [0,256)=w1_top [256,512)=w1_bot [512,768)=wq^T [768,1024)=wk^T [1024,1280)=wv^T
// bias1: [0,256)=b1, [256,512)=0, [512,1280)=in_b
// ---------------------------------------------------------------------------
__global__ void pack_kernel(const float* __restrict__ w1, const float* __restrict__ b1,
                            const float* __restrict__ in_w, const float* __restrict__ in_b,
                            const float* __restrict__ out_w,
                            float* __restrict__ wcat, float* __restrict__ bias1,
                            float* __restrict__ wot)
{
    int idx = blockIdx.x * 256 + threadIdx.x;
    if (idx < 327680) {
        int k = idx / 1280, c = idx % 1280;
        float v;
        if (c < 256)       v = w1[k * 256 + c];
        else if (c < 512)  v = w1[(256 + k) * 256 + (c - 256)];
        else if (c < 768)  v = in_w[(c - 512) * 256 + k];
        else if (c < 1024) v = in_w[(c - 768 + 256) * 256 + k];
        else               v = in_w[(c - 1024 + 512) * 256 + k];
        wcat[idx] = v;
    } else if (idx < 328960) {
        int c = idx - 327680;
        float v = (c < 256) ? b1[c] : (c < 512 ? 0.0f : in_b[c - 512]);
        bias1[c] = v;
    } else if (idx < 394496) {
        int i = idx - 328960;
        int k = i / 256, n = i % 256;
        wot[i] = out_w[n * 256 + k];
    }
}

// ---------------------------------------------------------------------------
// Tensor-core tf32 GEMM: C[M x Nc] = X[M x 256] * W[256 x Nc] (+bias)(opt relu)
// Block tile 128x128, K-chunk 32. 256 threads = 8 warps (2x4).
// ---------------------------------------------------------------------------
__global__ void gemm_tc(const float* __restrict__ X, int ldx,
                        const float* __restrict__ W, int ldw, int woff,
                        const float* __restrict__ bias, int boff,
                        float* __restrict__ C, int ldc, int relu)
{
    __shared__ uint32_t As[128][36];
    __shared__ uint32_t Bs[32][136];

    int t = threadIdx.x;
    int lane = t & 31, w = t >> 5;
    int gid = lane >> 2, tig = lane & 3;
    int wm = w >> 2, wn = w & 3;
    int m0 = blockIdx.x * 128, n0 = blockIdx.y * 128;

    float acc[4][4][4];
    #pragma unroll
    for (int mi = 0; mi < 4; mi++)
        #pragma unroll
        for (int ni = 0; ni < 4; ni++)
            #pragma unroll
            for (int q = 0; q < 4; q++) acc[mi][ni][q] = 0.0f;

    for (int k0 = 0; k0 < 256; k0 += 32) {
        #pragma unroll
        for (int i = 0; i < 4; i++) {
            int lin = i * 1024 + t * 4;
            int r = lin >> 5, c = lin & 31;
            float4 v = *(const float4*)(X + (size_t)(m0 + r) * ldx + k0 + c);
            As[r][c + 0] = f2tf32(v.x);
            As[r][c + 1] = f2tf32(v.y);
            As[r][c + 2] = f2tf32(v.z);
            As[r][c + 3] = f2tf32(v.w);
        }
        #pragma unroll
        for (int i = 0; i < 4; i++) {
            int lin = i * 1024 + t * 4;
            int r = lin >> 7, c = lin & 127;
            float4 v = *(const float4*)(W + (size_t)(k0 + r) * ldw + woff + n0 + c);
            Bs[r][c + 0] = f2tf32(v.x);
            Bs[r][c + 1] = f2tf32(v.y);
            Bs[r][c + 2] = f2tf32(v.z);
            Bs[r][c + 3] = f2tf32(v.w);
        }
        __syncthreads();

        #pragma unroll
        for (int ks = 0; ks < 4; ks++) {
            int kk = ks * 8;
            uint32_t a[4][4], b[4][2];
            #pragma unroll
            for (int mi = 0; mi < 4; mi++) {
                int rb = wm * 64 + mi * 16 + gid;
                a[mi][0] = As[rb][kk + tig];
                a[mi][1] = As[rb + 8][kk + tig];
                a[mi][2] = As[rb][kk + tig + 4];
                a[mi][3] = As[rb + 8][kk + tig + 4];
            }
            #pragma unroll
            for (int ni = 0; ni < 4; ni++) {
                int cb = wn * 32 + ni * 8 + gid;
                b[ni][0] = Bs[kk + tig][cb];
                b[ni][1] = Bs[kk + tig + 4][cb];
            }
            #pragma unroll
            for (int mi = 0; mi < 4; mi++)
                #pragma unroll
                for (int ni = 0; ni < 4; ni++)
                    mma_tf32(acc[mi][ni][0], acc[mi][ni][1], acc[mi][ni][2], acc[mi][ni][3],
                             a[mi][0], a[mi][1], a[mi][2], a[mi][3],
                             b[ni][0], b[ni][1]);
        }
        __syncthreads();
    }

    #pragma unroll
    for (int mi = 0; mi < 4; mi++) {
        int r0 = m0 + wm * 64 + mi * 16 + gid;
        #pragma unroll
        for (int ni = 0; ni < 4; ni++) {
            int col = n0 + wn * 32 + ni * 8 + 2 * tig;
            float bb0 = bias ? bias[boff + col]     : 0.0f;
            float bb1 = bias ? bias[boff + col + 1] : 0.0f;
            float2 v0, v1;
            v0.x = acc[mi][ni][0] + bb0; v0.y = acc[mi][ni][1] + bb1;
            v1.x = acc[mi][ni][2] + bb0; v1.y = acc[mi][ni][3] + bb1;
            if (relu) {
                v0.x = fmaxf(v0.x, 0.0f); v0.y = fmaxf(v0.y, 0.0f);
                v1.x = fmaxf(v1.x, 0.0f); v1.y = fmaxf(v1.y, 0.0f);
            }
            *(float2*)(C + (size_t)r0 * ldc + col)       = v0;
            *(float2*)(C + (size_t)(r0 + 8) * ldc + col) = v1;
        }
    }
}

// ---------------------------------------------------------------------------
// Edge scatter: one warp per (modality, batch, edge).
// ---------------------------------------------------------------------------
__global__ void edge_kernel(const float* __restrict__ proj,
                            const int* __restrict__ src, const int* __restrict__ dst,
                            const float* __restrict__ w2, const float* __restrict__ b2p,
                            float* __restrict__ wout)
{
    int gw   = (blockIdx.x * blockDim.x + threadIdx.x) >> 5;
    int lane = threadIdx.x & 31;
    int e = gw & 16383;
    int b = (gw >> 14) & 15;
    int m = gw >> 18;
    int s = src[e], d = dst[e];

    const float4* ar = (const float4*)(proj + ((size_t)m * 8192 + b * 512 + s) * 1280);
    const float4* br = (const float4*)(proj + ((size_t)m * 8192 + b * 512 + d) * 1280 + 256);
    const float4* w4 = (const float4*)w2;

    float p = 0.0f;
    #pragma unroll
    for (int u = 0; u < 2; u++) {
        int idx = u * 32 + lane;
        float4 a = ar[idx], bb = br[idx], w = w4[idx];
        p += fmaxf(a.x + bb.x, 0.0f) * w.x;
        p += fmaxf(a.y + bb.y, 0.0f) * w.y;
        p += fmaxf(a.z + bb.z, 0.0f) * w.z;
        p += fmaxf(a.w + bb.w, 0.0f) * w.w;
    }
    #pragma unroll
    for (int off = 16; off > 0; off >>= 1)
        p += __shfl_xor_sync(0xFFFFFFFFu, p, off);
    if (lane == 0) {
        float v = 1.0f / (1.0f + __expf(-(p + b2p[0])));
        wout[(size_t)m * 4194304 + (size_t)b * 262144 + (size_t)s * 512 + d] = v;
    }
}

// ---------------------------------------------------------------------------
// Tensor-core attention (pre out-proj). Block = (128-row chunk, head, batch).
// 8 warps x 16 query rows. K/V staged in smem as tf32 (strides 36 / 40,
// conflict-free fragment reads). Scores via m16n8k8 tf32 mma; no max
// subtraction (scores are O(1): tiny projections + sigmoid mask in [0,1]);
// P rounded to tf32 in per-warp smem (stride 68), PV via mma.
// Smem: 512*36 + 512*40 + 8*16*68 words = 190464 B.
// ---------------------------------------------------------------------------
__global__ void attn_kernel(const float* __restrict__ qbuf, int qld, int qoff,
                            const float* __restrict__ kbuf, int kld, int koff,
                            const float* __restrict__ vbuf, int vld, int voff,
                            const float* __restrict__ mask,
                            float* __restrict__ ctx)
{
    extern __shared__ uint32_t sm[];
    uint32_t* Ks = sm;               // [512][36]
    uint32_t* Vs = sm + 18432;       // [512][40]
    uint32_t* Pw = sm + 38912;       // 8 warps x [16][68]

    int b = blockIdx.z, h = blockIdx.y, chunk = blockIdx.x;
    int t = threadIdx.x, lane = t & 31, w = t >> 5;
    int gid = lane >> 2, tig = lane & 3;

    // Stage K, V (tf32) -- rows 16B-aligned for uint4 stores.
    for (int i = t; i < 4096; i += 256) {
        int row = i >> 3, c4 = (i & 7) * 4;
        size_t rk = (size_t)(b * 512 + row);
        float4 kv = *(const float4*)(kbuf + rk * kld + koff + h * 32 + c4);
        uint4 kt; kt.x = f2tf32(kv.x); kt.y = f2tf32(kv.y); kt.z = f2tf32(kv.z); kt.w = f2tf32(kv.w);
        *(uint4*)&Ks[row * 36 + c4] = kt;
        float4 vv = *(const float4*)(vbuf + rk * vld + voff + h * 32 + c4);
        uint4 vt; vt.x = f2tf32(vv.x); vt.y = f2tf32(vv.y); vt.z = f2tf32(vv.z); vt.w = f2tf32(vv.w);
        *(uint4*)&Vs[row * 40 + c4] = vt;
    }
    __syncthreads();

    uint32_t* Ps = Pw + w * 1088;
    int i0 = chunk * 128 + w * 16;
    const float scale = 0.17677669529663687f;  // 1/sqrt(32)

    // Q fragments, pre-scaled
    uint32_t qa[4][4];
    {
        const float* q0p = qbuf + (size_t)(b * 512 + i0 + gid) * qld + qoff + h * 32;
        const float* q1p = q0p + (size_t)8 * qld;
        #pragma unroll
        for (int ks = 0; ks < 4; ks++) {
            qa[ks][0] = f2tf32(q0p[ks * 8 + tig] * scale);
            qa[ks][1] = f2tf32(q1p[ks * 8 + tig] * scale);
            qa[ks][2] = f2tf32(q0p[ks * 8 + tig + 4] * scale);
            qa[ks][3] = f2tf32(q1p[ks * 8 + tig + 4] * scale);
        }
    }

    const float* mrow0 = mask ? mask + (size_t)b * 262144 + (size_t)(i0 + gid) * 512 : nullptr;
    const float* mrow1 = mrow0 ? mrow0 + 8 * 512 : nullptr;

    float oacc[4][4];
    #pragma unroll
    for (int vt = 0; vt < 4; vt++)
        #pragma unroll
        for (int q = 0; q < 4; q++) oacc[vt][q] = 0.0f;
    float rsum0 = 0.0f, rsum1 = 0.0f;

    for (int kc = 0; kc < 8; kc++) {
        float sacc[8][4];
        #pragma unroll
        for (int nt = 0; nt < 8; nt++)
            #pragma unroll
            for (int q = 0; q < 4; q++) sacc[nt][q] = 0.0f;

        #pragma unroll
        for (int ks = 0; ks < 4; ks++) {
            #pragma unroll
            for (int nt = 0; nt < 8; nt++) {
                int key = kc * 64 + nt * 8 + gid;
                uint32_t b0 = Ks[key * 36 + ks * 8 + tig];
                uint32_t b1 = Ks[key * 36 + ks * 8 + tig + 4];
                mma_tf32(sacc[nt][0], sacc[nt][1], sacc[nt][2], sacc[nt][3],
                         qa[ks][0], qa[ks][1], qa[ks][2], qa[ks][3], b0, b1);
            }
        }

        // exp (+mask), accumulate row sums, stash P (tf32) in warp smem
        #pragma unroll
        for (int nt = 0; nt < 8; nt++) {
            int col = kc * 64 + nt * 8 + 2 * tig;
            float s0 = sacc[nt][0], s1 = sacc[nt][1];
            float s2 = sacc[nt][2], s3 = sacc[nt][3];
            if (mrow0) {
                float2 m0 = *(const float2*)(mrow0 + col);
                float2 m1 = *(const float2*)(mrow1 + col);
                s0 += m0.x; s1 += m0.y; s2 += m1.x; s3 += m1.y;
            }
            float p0 = __expf(s0), p1 = __expf(s1);
            float p2 = __expf(s2), p3 = __expf(s3);
            rsum0 += p0 + p1;
            rsum1 += p2 + p3;
            uint2 u0; u0.x = f2tf32(p0); u0.y = f2tf32(p1);
            uint2 u1; u1.x = f2tf32(p2); u1.y = f2tf32(p3);
            *(uint2*)&Ps[gid * 68 + nt * 8 + 2 * tig]       = u0;
            *(uint2*)&Ps[(gid + 8) * 68 + nt * 8 + 2 * tig] = u1;
        }
        __syncwarp();

        // P @ V
        #pragma unroll
        for (int ks2 = 0; ks2 < 8; ks2++) {
            uint32_t a0 = Ps[gid * 68 + ks2 * 8 + tig];
            uint32_t a1 = Ps[(gid + 8) * 68 + ks2 * 8 + tig];
            uint32_t a2 = Ps[gid * 68 + ks2 * 8 + tig + 4];
            uint32_t a3 = Ps[(gid + 8) * 68 + ks2 * 8 + tig + 4];
            int keyb = kc * 64 + ks2 * 8;
            #pragma unroll
            for (int vt = 0; vt < 4; vt++) {
                uint32_t b0 = Vs[(keyb + tig) * 40 + vt * 8 + gid];
                uint32_t b1 = Vs[(keyb + tig + 4) * 40 + vt * 8 + gid];
                mma_tf32(oacc[vt][0], oacc[vt][1], oacc[vt][2], oacc[vt][3],
                         a0, a1, a2, a3, b0, b1);
            }
        }
        __syncwarp();
    }

    // reduce row sums over the 4-lane quad (same gid, tig = bits 0-1)
    rsum0 += __shfl_xor_sync(0xFFFFFFFFu, rsum0, 1);
    rsum0 += __shfl_xor_sync(0xFFFFFFFFu, rsum0, 2);
    rsum1 += __shfl_xor_sync(0xFFFFFFFFu, rsum1, 1);
    rsum1 += __shfl_xor_sync(0xFFFFFFFFu, rsum1, 2);
    float inv0 = 1.0f / rsum0, inv1 = 1.0f / rsum1;

    size_t r0 = (size_t)(b * 512 + i0 + gid) * 256 + h * 32;
    size_t r1 = r0 + (size_t)8 * 256;
    #pragma unroll
    for (int vt = 0; vt < 4; vt++) {
        float2 v0; v0.x = oacc[vt][0] * inv0; v0.y = oacc[vt][1] * inv0;
        float2 v1; v1.x = oacc[vt][2] * inv1; v1.y = oacc[vt][3] * inv1;
        *(float2*)(ctx + r0 + vt * 8 + 2 * tig) = v0;
        *(float2*)(ctx + r1 + vt * 8 + 2 * tig) = v1;
    }
}

// ---------------------------------------------------------------------------
__global__ void cons_reduce(const float* __restrict__ H, const float* __restrict__ cw2,
                            const float* __restrict__ cb2, float* __restrict__ out)
{
    int gw   = (blockIdx.x * blockDim.x + threadIdx.x) >> 5;  // row 0..16383
    int lane = threadIdx.x & 31;
    const float4* h4 = (const float4*)(H + (size_t)gw * 256);
    const float4* w4 = (const float4*)cw2;
    float p = 0.0f;
    #pragma unroll
    for (int u = 0; u < 2; u++) {
        int idx = u * 32 + lane;
        float4 a = h4[idx], w = w4[idx];
        p += a.x * w.x + a.y * w.y + a.z * w.z + a.w * w.w;
    }
    #pragma unroll
    for (int off = 16; off > 0; off >>= 1)
        p += __shfl_xor_sync(0xFFFFFFFFu, p, off);
    if (lane == 0)
        out[gw] = 1.0f / (1.0f + __expf(-(p + cb2[0])));
}

// ---------------------------------------------------------------------------
extern "C" void kernel_launch(void* const* d_in, const int* in_sizes, int n_in,
                              void* d_out, int out_size)
{
    const float* img   = (const float*)d_in[0];
    const float* txt   = (const float*)d_in[1];
    const int*   src   = (const int*)  d_in[2];
    const int*   dst   = (const int*)  d_in[3];
    const float* w1    = (const float*)d_in[4];
    const float* b1    = (const float*)d_in[5];
    const float* w2    = (const float*)d_in[6];
    const float* b2    = (const float*)d_in[7];
    const float* in_w  = (const float*)d_in[8];
    const float* in_b  = (const float*)d_in[9];
    const float* out_w = (const float*)d_in[10];
    const float* out_b = (const float*)d_in[11];
    const float* cw1   = (const float*)d_in[12];
    const float* cb1   = (const float*)d_in[13];
    const float* cw2   = (const float*)d_in[14];
    const float* cb2   = (const float*)d_in[15];
    float* out = (float*)d_out;

    float* S = nullptr;
    cudaGetSymbolAddress((void**)&S, g_scratch);

    float* wcat  = S + OFF_WCAT;
    float* bias1 = S + OFF_BIAS1;
    float* wot   = S + OFF_WOT;
    float* proj  = S + OFF_PROJ;
    float* ctx   = S + OFF_CTX;
    float* qc    = S + OFF_QC;
    float* kvc   = S + OFF_KVC;
    float* ctx2  = S + OFF_CTX2;
    float* Hbuf  = proj;  // reuse after attention consumes proj

    float* att_img = out;
    float* att_txt = out + 2097152;
    float* cross   = out + 4194304;
    float* wimg    = out + 6291456;
    float* cons    = out + 14680064;

    const int ATTN_SMEM = 190464;
    cudaFuncSetAttribute(attn_kernel, cudaFuncAttributeMaxDynamicSharedMemorySize, ATTN_SMEM);

    // 1. pack fused weights
    pack_kernel<<<1541, 256>>>(w1, b1, in_w, in_b, out_w, wcat, bias1, wot);

    // 2. zero both weight matrices (img + text adjacent)
    cudaMemsetAsync(wimg, 0, (size_t)8388608 * 4);

    // 3. fused node projections: A|Bm|Q|K|V per modality (tf32 tensor cores)
    gemm_tc<<<dim3(64, 10), 256>>>(img, 256, wcat, 1280, 0, bias1, 0, proj, 1280, 0);
    gemm_tc<<<dim3(64, 10), 256>>>(txt, 256, wcat, 1280, 0, bias1, 0,
                                   proj + (size_t)8192 * 1280, 1280, 0);

    // 4. per-edge causal weights (both modalities)
    edge_kernel<<<65536, 256>>>(proj, src, dst, w2, b2, wimg);

    // 5. masked self-attention (img, text) -> ctx (pre out-proj)
    attn_kernel<<<dim3(4, 8, 16), 256, ATTN_SMEM>>>(
        proj, 1280, 512, proj, 1280, 768, proj, 1280, 1024, wimg, ctx);
    attn_kernel<<<dim3(4, 8, 16), 256, ATTN_SMEM>>>(
        proj + (size_t)8192 * 1280, 1280, 512,
        proj + (size_t)8192 * 1280, 1280, 768,
        proj + (size_t)8192 * 1280, 1280, 1024,
        wimg + 4194304, ctx + (size_t)8192 * 256);

    // 6. out-proj for both modalities -> attended_*
    gemm_tc<<<dim3(128, 2), 256>>>(ctx, 256, wot, 256, 0, out_b, 0, att_img, 256, 0);

    // 7. consistency
    gemm_tc<<<dim3(128, 2), 256>>>(att_img, 256, cw1, 256, 0, cb1, 0, Hbuf, 256, 1);
    cons_reduce<<<2048, 256>>>(Hbuf, cw2, cb2, cons);

    // 8. cross-modal
    gemm_tc<<<dim3(64, 2), 256>>>(att_img, 256, wcat, 1280, 512, bias1, 512, qc, 256, 0);
    gemm_tc<<<dim3(64, 4), 256>>>(att_txt, 256, wcat, 1280, 768, bias1, 768, kvc, 512, 0);
    attn_kernel<<<dim3(4, 8, 16), 256, ATTN_SMEM>>>(
        qc, 256, 0, kvc, 512, 0, kvc, 512, 256, nullptr, ctx2);
    gemm_tc<<<dim3(64, 2), 256>>>(ctx2, 256, wot, 256, 0, out_b, 0, cross, 256, 0);
}

// round 4
// speedup vs baseline: 2.3896x; 1.1977x over previous
#include <cuda_runtime.h>
#include <cuda_bf16.h>
#include <cstddef>
#include <cstdint>

// Problem constants: B=16, N=512, D=256, H=8, DH=32, E=16384
// d_out layout (floats):
//   attended_img   [0,        2097152)
//   attended_text  [2097152,  4194304)
//   cross_modal    [4194304,  6291456)
//   img_weights    [6291456, 10485760)
//   text_weights   [10485760,14680064)
//   img_cons       [14680064,14688256)
//   text_cons      [14688256,14696448)

#define OFF_WCAT   0u             // 256*1280
#define OFF_BIAS1  327680u        // 1280
#define OFF_WOT    328960u        // 256*256
#define OFF_PROJ   394496u        // 16384*1280  (reused as H for consistency)
#define OFF_CTX    21366016u      // 16384*256
#define OFF_QC     25560320u      // 8192*256
#define OFF_KVC    27657472u      // 8192*512
#define OFF_CTX2   31851776u      // 8192*256
#define SCRATCH_FLOATS 33948928u

__device__ float g_scratch[SCRATCH_FLOATS];

// ---------------------------------------------------------------------------
__device__ __forceinline__ uint32_t f2tf32(float f) {
    uint32_t r;
    asm("cvt.rna.tf32.f32 %0, %1;" : "=r"(r) : "f"(f));
    return r;
}

__device__ __forceinline__ void mma_tf32(float& d0, float& d1, float& d2, float& d3,
                                         uint32_t a0, uint32_t a1, uint32_t a2, uint32_t a3,
                                         uint32_t b0, uint32_t b1)
{
    asm volatile(
        "mma.sync.aligned.m16n8k8.row.col.f32.tf32.tf32.f32 "
        "{%0,%1,%2,%3}, {%4,%5,%6,%7}, {%8,%9}, {%0,%1,%2,%3};"
        : "+f"(d0), "+f"(d1), "+f"(d2), "+f"(d3)
        : "r"(a0), "r"(a1), "r"(a2), "r"(a3), "r"(b0), "r"(b1));
}

// ---------------------------------------------------------------------------
// Pack: wcat[k][c] (256 x 1280), bias1[1280], wot = out_w^T (256x256)
// ---------------------------------------------------------------------------
__global__ void pack_kernel(const float* __restrict__ w1, const float* __restrict__ b1,
                            const float* __restrict__ in_w, const float* __restrict__ in_b,
                            const float* __restrict__ out_w,
                            float* __restrict__ wcat, float* __restrict__ bias1,
                            float* __restrict__ wot)
{
    int idx = blockIdx.x * 256 + threadIdx.x;
    if (idx < 327680) {
        int k = idx / 1280, c = idx % 1280;
        float v;
        if (c < 256)       v = w1[k * 256 + c];
        else if (c < 512)  v = w1[(256 + k) * 256 + (c - 256)];
        else if (c < 768)  v = in_w[(c - 512) * 256 + k];
        else if (c < 1024) v = in_w[(c - 768 + 256) * 256 + k];
        else               v = in_w[(c - 1024 + 512) * 256 + k];
        wcat[idx] = v;
    } else if (idx < 328960) {
        int c = idx - 327680;
        float v = (c < 256) ? b1[c] : (c < 512 ? 0.0f : in_b[c - 512]);
        bias1[c] = v;
    } else if (idx < 394496) {
        int i = idx - 328960;
        int k = i / 256, n = i % 256;
        wot[i] = out_w[n * 256 + k];
    }
}

// ---------------------------------------------------------------------------
// Tensor-core tf32 GEMM with register-prefetch double buffering.
// C[z][M x Nc] = X_z[M x 256] * W[256 x Nc] (+bias)(opt relu)
// Block tile 128x128, K-chunk 32. 256 threads = 8 warps (2x4).
// grid = (M/128, Nc/128, Z); X = z ? X1 : X0; C += z*czstride.
// ---------------------------------------------------------------------------
__global__ void gemm_tc(const float* __restrict__ X0, const float* __restrict__ X1,
                        int ldx,
                        const float* __restrict__ W, int ldw, int woff,
                        const float* __restrict__ bias, int boff,
                        float* __restrict__ C, int ldc, size_t czstride, int relu)
{
    __shared__ uint32_t As[128][36];
    __shared__ uint32_t Bs[32][136];

    int z = blockIdx.z;
    const float* X = z ? X1 : X0;
    float* Cz = C + (size_t)z * czstride;

    int t = threadIdx.x;
    int lane = t & 31, w = t >> 5;
    int gid = lane >> 2, tig = lane & 3;
    int wm = w >> 2, wn = w & 3;
    int m0 = blockIdx.x * 128, n0 = blockIdx.y * 128;

    // per-thread staging coords (constant across chunks)
    int ar[4], ac[4], br4[4], bc4[4];
    #pragma unroll
    for (int i = 0; i < 4; i++) {
        int lin = i * 1024 + t * 4;
        ar[i] = lin >> 5;  ac[i]  = lin & 31;
        br4[i] = lin >> 7; bc4[i] = lin & 127;
    }

    float acc[4][4][4];
    #pragma unroll
    for (int mi = 0; mi < 4; mi++)
        #pragma unroll
        for (int ni = 0; ni < 4; ni++)
            #pragma unroll
            for (int q = 0; q < 4; q++) acc[mi][ni][q] = 0.0f;

    float4 xa[4], wb[4];
    // prefetch chunk 0
    #pragma unroll
    for (int i = 0; i < 4; i++) {
        xa[i] = *(const float4*)(X + (size_t)(m0 + ar[i]) * ldx + ac[i]);
        wb[i] = *(const float4*)(W + (size_t)br4[i] * ldw + woff + n0 + bc4[i]);
    }

    for (int ch = 0; ch < 8; ch++) {
        // store staged regs (cvt to tf32)
        #pragma unroll
        for (int i = 0; i < 4; i++) {
            As[ar[i]][ac[i] + 0] = f2tf32(xa[i].x);
            As[ar[i]][ac[i] + 1] = f2tf32(xa[i].y);
            As[ar[i]][ac[i] + 2] = f2tf32(xa[i].z);
            As[ar[i]][ac[i] + 3] = f2tf32(xa[i].w);
            Bs[br4[i]][bc4[i] + 0] = f2tf32(wb[i].x);
            Bs[br4[i]][bc4[i] + 1] = f2tf32(wb[i].y);
            Bs[br4[i]][bc4[i] + 2] = f2tf32(wb[i].z);
            Bs[br4[i]][bc4[i] + 3] = f2tf32(wb[i].w);
        }
        __syncthreads();

        // issue next chunk's loads (latency hidden by compute below)
        if (ch < 7) {
            int k0 = (ch + 1) * 32;
            #pragma unroll
            for (int i = 0; i < 4; i++) {
                xa[i] = *(const float4*)(X + (size_t)(m0 + ar[i]) * ldx + k0 + ac[i]);
                wb[i] = *(const float4*)(W + (size_t)(k0 + br4[i]) * ldw + woff + n0 + bc4[i]);
            }
        }

        #pragma unroll
        for (int ks = 0; ks < 4; ks++) {
            int kk = ks * 8;
            uint32_t a[4][4], b[4][2];
            #pragma unroll
            for (int mi = 0; mi < 4; mi++) {
                int rb = wm * 64 + mi * 16 + gid;
                a[mi][0] = As[rb][kk + tig];
                a[mi][1] = As[rb + 8][kk + tig];
                a[mi][2] = As[rb][kk + tig + 4];
                a[mi][3] = As[rb + 8][kk + tig + 4];
            }
            #pragma unroll
            for (int ni = 0; ni < 4; ni++) {
                int cb = wn * 32 + ni * 8 + gid;
                b[ni][0] = Bs[kk + tig][cb];
                b[ni][1] = Bs[kk + tig + 4][cb];
            }
            #pragma unroll
            for (int mi = 0; mi < 4; mi++)
                #pragma unroll
                for (int ni = 0; ni < 4; ni++)
                    mma_tf32(acc[mi][ni][0], acc[mi][ni][1], acc[mi][ni][2], acc[mi][ni][3],
                             a[mi][0], a[mi][1], a[mi][2], a[mi][3],
                             b[ni][0], b[ni][1]);
        }
        __syncthreads();
    }

    #pragma unroll
    for (int mi = 0; mi < 4; mi++) {
        int r0 = m0 + wm * 64 + mi * 16 + gid;
        #pragma unroll
        for (int ni = 0; ni < 4; ni++) {
            int col = n0 + wn * 32 + ni * 8 + 2 * tig;
            float bb0 = bias ? bias[boff + col]     : 0.0f;
            float bb1 = bias ? bias[boff + col + 1] : 0.0f;
            float2 v0, v1;
            v0.x = acc[mi][ni][0] + bb0; v0.y = acc[mi][ni][1] + bb1;
            v1.x = acc[mi][ni][2] + bb0; v1.y = acc[mi][ni][3] + bb1;
            if (relu) {
                v0.x = fmaxf(v0.x, 0.0f); v0.y = fmaxf(v0.y, 0.0f);
                v1.x = fmaxf(v1.x, 0.0f); v1.y = fmaxf(v1.y, 0.0f);
            }
            *(float2*)(Cz + (size_t)r0 * ldc + col)       = v0;
            *(float2*)(Cz + (size_t)(r0 + 8) * ldc + col) = v1;
        }
    }
}

// ---------------------------------------------------------------------------
// Edge scatter: one warp per (modality, batch, edge).
// ---------------------------------------------------------------------------
__global__ void edge_kernel(const float* __restrict__ proj,
                            const int* __restrict__ src, const int* __restrict__ dst,
                            const float* __restrict__ w2, const float* __restrict__ b2p,
                            float* __restrict__ wout)
{
    int gw   = (blockIdx.x * blockDim.x + threadIdx.x) >> 5;
    int lane = threadIdx.x & 31;
    int e = gw & 16383;
    int b = (gw >> 14) & 15;
    int m = gw >> 18;
    int s = src[e], d = dst[e];

    const float4* ar = (const float4*)(proj + ((size_t)m * 8192 + b * 512 + s) * 1280);
    const float4* br = (const float4*)(proj + ((size_t)m * 8192 + b * 512 + d) * 1280 + 256);
    const float4* w4 = (const float4*)w2;

    float p = 0.0f;
    #pragma unroll
    for (int u = 0; u < 2; u++) {
        int idx = u * 32 + lane;
        float4 a = ar[idx], bb = br[idx], w = w4[idx];
        p += fmaxf(a.x + bb.x, 0.0f) * w.x;
        p += fmaxf(a.y + bb.y, 0.0f) * w.y;
        p += fmaxf(a.z + bb.z, 0.0f) * w.z;
        p += fmaxf(a.w + bb.w, 0.0f) * w.w;
    }
    #pragma unroll
    for (int off = 16; off > 0; off >>= 1)
        p += __shfl_xor_sync(0xFFFFFFFFu, p, off);
    if (lane == 0) {
        float v = 1.0f / (1.0f + __expf(-(p + b2p[0])));
        wout[(size_t)m * 4194304 + (size_t)b * 262144 + (size_t)s * 512 + d] = v;
    }
}

// ---------------------------------------------------------------------------
// Tensor-core attention. grid = (4 chunks, 8 heads, Z); z -> (b = z&15, mz = z>>4).
// mz selects modality via *zstride offsets. Smem 190464 B.
// ---------------------------------------------------------------------------
__global__ void attn_kernel(const float* __restrict__ qbuf, int qld, int qoff, size_t qzs,
                            const float* __restrict__ kbuf, int kld, int koff, size_t kzs,
                            const float* __restrict__ vbuf, int vld, int voff, size_t vzs,
                            const float* __restrict__ mask, size_t mzs,
                            float* __restrict__ ctx, size_t czs)
{
    extern __shared__ uint32_t sm[];
    uint32_t* Ks = sm;               // [512][36]
    uint32_t* Vs = sm + 18432;       // [512][40]
    uint32_t* Pw = sm + 38912;       // 8 warps x [16][68]

    int zb = blockIdx.z;
    int b = zb & 15, mz = zb >> 4;
    const float* Q = qbuf + (size_t)mz * qzs;
    const float* K = kbuf + (size_t)mz * kzs;
    const float* V = vbuf + (size_t)mz * vzs;
    const float* M = mask ? mask + (size_t)mz * mzs : nullptr;
    float* O = ctx + (size_t)mz * czs;

    int h = blockIdx.y, chunk = blockIdx.x;
    int t = threadIdx.x, lane = t & 31, w = t >> 5;
    int gid = lane >> 2, tig = lane & 3;

    for (int i = t; i < 4096; i += 256) {
        int row = i >> 3, c4 = (i & 7) * 4;
        size_t rk = (size_t)(b * 512 + row);
        float4 kv = *(const float4*)(K + rk * kld + koff + h * 32 + c4);
        uint4 kt; kt.x = f2tf32(kv.x); kt.y = f2tf32(kv.y); kt.z = f2tf32(kv.z); kt.w = f2tf32(kv.w);
        *(uint4*)&Ks[row * 36 + c4] = kt;
        float4 vv = *(const float4*)(V + rk * vld + voff + h * 32 + c4);
        uint4 vt; vt.x = f2tf32(vv.x); vt.y = f2tf32(vv.y); vt.z = f2tf32(vv.z); vt.w = f2tf32(vv.w);
        *(uint4*)&Vs[row * 40 + c4] = vt;
    }
    __syncthreads();

    uint32_t* Ps = Pw + w * 1088;
    int i0 = chunk * 128 + w * 16;
    const float scale = 0.17677669529663687f;  // 1/sqrt(32)

    uint32_t qa[4][4];
    {
        const float* q0p = Q + (size_t)(b * 512 + i0 + gid) * qld + qoff + h * 32;
        const float* q1p = q0p + (size_t)8 * qld;
        #pragma unroll
        for (int ks = 0; ks < 4; ks++) {
            qa[ks][0] = f2tf32(q0p[ks * 8 + tig] * scale);
            qa[ks][1] = f2tf32(q1p[ks * 8 + tig] * scale);
            qa[ks][2] = f2tf32(q0p[ks * 8 + tig + 4] * scale);
            qa[ks][3] = f2tf32(q1p[ks * 8 + tig + 4] * scale);
        }
    }

    const float* mrow0 = M ? M + (size_t)b * 262144 + (size_t)(i0 + gid) * 512 : nullptr;
    const float* mrow1 = mrow0 ? mrow0 + 8 * 512 : nullptr;

    float oacc[4][4];
    #pragma unroll
    for (int vt = 0; vt < 4; vt++)
        #pragma unroll
        for (int q = 0; q < 4; q++) oacc[vt][q] = 0.0f;
    float rsum0 = 0.0f, rsum1 = 0.0f;

    for (int kc = 0; kc < 8; kc++) {
        // mask prefetch for this chunk (LDG latency hidden by the mma block)
        float2 mv0[8], mv1[8];
        if (mrow0) {
            #pragma unroll
            for (int nt = 0; nt < 8; nt++) {
                int col = kc * 64 + nt * 8 + 2 * tig;
                mv0[nt] = *(const float2*)(mrow0 + col);
                mv1[nt] = *(const float2*)(mrow1 + col);
            }
        }

        float sacc[8][4];
        #pragma unroll
        for (int nt = 0; nt < 8; nt++)
            #pragma unroll
            for (int q = 0; q < 4; q++) sacc[nt][q] = 0.0f;

        #pragma unroll
        for (int ks = 0; ks < 4; ks++) {
            #pragma unroll
            for (int nt = 0; nt < 8; nt++) {
                int key = kc * 64 + nt * 8 + gid;
                uint32_t b0 = Ks[key * 36 + ks * 8 + tig];
                uint32_t b1 = Ks[key * 36 + ks * 8 + tig + 4];
                mma_tf32(sacc[nt][0], sacc[nt][1], sacc[nt][2], sacc[nt][3],
                         qa[ks][0], qa[ks][1], qa[ks][2], qa[ks][3], b0, b1);
            }
        }

        #pragma unroll
        for (int nt = 0; nt < 8; nt++) {
            float s0 = sacc[nt][0], s1 = sacc[nt][1];
            float s2 = sacc[nt][2], s3 = sacc[nt][3];
            if (mrow0) {
                s0 += mv0[nt].x; s1 += mv0[nt].y;
                s2 += mv1[nt].x; s3 += mv1[nt].y;
            }
            float p0 = __expf(s0), p1 = __expf(s1);
            float p2 = __expf(s2), p3 = __expf(s3);
            rsum0 += p0 + p1;
            rsum1 += p2 + p3;
            uint2 u0; u0.x = f2tf32(p0); u0.y = f2tf32(p1);
            uint2 u1; u1.x = f2tf32(p2); u1.y = f2tf32(p3);
            *(uint2*)&Ps[gid * 68 + nt * 8 + 2 * tig]       = u0;
            *(uint2*)&Ps[(gid + 8) * 68 + nt * 8 + 2 * tig] = u1;
        }
        __syncwarp();

        #pragma unroll
        for (int ks2 = 0; ks2 < 8; ks2++) {
            uint32_t a0 = Ps[gid * 68 + ks2 * 8 + tig];
            uint32_t a1 = Ps[(gid + 8) * 68 + ks2 * 8 + tig];
            uint32_t a2 = Ps[gid * 68 + ks2 * 8 + tig + 4];
            uint32_t a3 = Ps[(gid + 8) * 68 + ks2 * 8 + tig + 4];
            int keyb = kc * 64 + ks2 * 8;
            #pragma unroll
            for (int vt = 0; vt < 4; vt++) {
                uint32_t b0 = Vs[(keyb + tig) * 40 + vt * 8 + gid];
                uint32_t b1 = Vs[(keyb + tig + 4) * 40 + vt * 8 + gid];
                mma_tf32(oacc[vt][0], oacc[vt][1], oacc[vt][2], oacc[vt][3],
                         a0, a1, a2, a3, b0, b1);
            }
        }
        __syncwarp();
    }

    rsum0 += __shfl_xor_sync(0xFFFFFFFFu, rsum0, 1);
    rsum0 += __shfl_xor_sync(0xFFFFFFFFu, rsum0, 2);
    rsum1 += __shfl_xor_sync(0xFFFFFFFFu, rsum1, 1);
    rsum1 += __shfl_xor_sync(0xFFFFFFFFu, rsum1, 2);
    float inv0 = 1.0f / rsum0, inv1 = 1.0f / rsum1;

    size_t r0 = (size_t)(b * 512 + i0 + gid) * 256 + h * 32;
    size_t r1 = r0 + (size_t)8 * 256;
    #pragma unroll
    for (int vt = 0; vt < 4; vt++) {
        float2 v0; v0.x = oacc[vt][0] * inv0; v0.y = oacc[vt][1] * inv0;
        float2 v1; v1.x = oacc[vt][2] * inv1; v1.y = oacc[vt][3] * inv1;
        *(float2*)(O + r0 + vt * 8 + 2 * tig) = v0;
        *(float2*)(O + r1 + vt * 8 + 2 * tig) = v1;
    }
}

// ---------------------------------------------------------------------------
__global__ void cons_reduce(const float* __restrict__ H, const float* __restrict__ cw2,
                            const float* __restrict__ cb2, float* __restrict__ out)
{
    int gw   = (blockIdx.x * blockDim.x + threadIdx.x) >> 5;
    int lane = threadIdx.x & 31;
    const float4* h4 = (const float4*)(H + (size_t)gw * 256);
    const float4* w4 = (const float4*)cw2;
    float p = 0.0f;
    #pragma unroll
    for (int u = 0; u < 2; u++) {
        int idx = u * 32 + lane;
        float4 a = h4[idx], w = w4[idx];
        p += a.x * w.x + a.y * w.y + a.z * w.z + a.w * w.w;
    }
    #pragma unroll
    for (int off = 16; off > 0; off >>= 1)
        p += __shfl_xor_sync(0xFFFFFFFFu, p, off);
    if (lane == 0)
        out[gw] = 1.0f / (1.0f + __expf(-(p + cb2[0])));
}

// ---------------------------------------------------------------------------
extern "C" void kernel_launch(void* const* d_in, const int* in_sizes, int n_in,
                              void* d_out, int out_size)
{
    const float* img   = (const float*)d_in[0];
    const float* txt   = (const float*)d_in[1];
    const int*   src   = (const int*)  d_in[2];
    const int*   dst   = (const int*)  d_in[3];
    const float* w1    = (const float*)d_in[4];
    const float* b1    = (const float*)d_in[5];
    const float* w2    = (const float*)d_in[6];
    const float* b2    = (const float*)d_in[7];
    const float* in_w  = (const float*)d_in[8];
    const float* in_b  = (const float*)d_in[9];
    const float* out_w = (const float*)d_in[10];
    const float* out_b = (const float*)d_in[11];
    const float* cw1   = (const float*)d_in[12];
    const float* cb1   = (const float*)d_in[13];
    const float* cw2   = (const float*)d_in[14];
    const float* cb2   = (const float*)d_in[15];
    float* out = (float*)d_out;

    float* S = nullptr;
    cudaGetSymbolAddress((void**)&S, g_scratch);

    float* wcat  = S + OFF_WCAT;
    float* bias1 = S + OFF_BIAS1;
    float* wot   = S + OFF_WOT;
    float* proj  = S + OFF_PROJ;
    float* ctx   = S + OFF_CTX;
    float* qc    = S + OFF_QC;
    float* kvc   = S + OFF_KVC;
    float* ctx2  = S + OFF_CTX2;
    float* Hbuf  = proj;  // reuse after attention consumes proj

    float* att_img = out;
    float* att_txt = out + 2097152;
    float* cross   = out + 4194304;
    float* wimg    = out + 6291456;
    float* cons    = out + 14680064;

    const int ATTN_SMEM = 190464;
    cudaFuncSetAttribute(attn_kernel, cudaFuncAttributeMaxDynamicSharedMemorySize, ATTN_SMEM);

    const size_t PSTRIDE = (size_t)8192 * 1280;   // proj per-modality stride
    const size_t CSTRIDE = (size_t)8192 * 256;    // ctx per-modality stride
    const size_t MSTRIDE = (size_t)4194304;       // mask per-modality stride

    // 1. pack fused weights
    pack_kernel<<<1541, 256>>>(w1, b1, in_w, in_b, out_w, wcat, bias1, wot);

    // 2. zero both weight matrices
    cudaMemsetAsync(wimg, 0, (size_t)8388608 * 4);

    // 3. fused node projections (both modalities in one launch, grid.z=2)
    gemm_tc<<<dim3(64, 10, 2), 256>>>(img, txt, 256, wcat, 1280, 0, bias1, 0,
                                      proj, 1280, PSTRIDE, 0);

    // 4. per-edge causal weights (both modalities)
    edge_kernel<<<65536, 256>>>(proj, src, dst, w2, b2, wimg);

    // 5. masked self-attention, both modalities in one launch (grid.z=32)
    attn_kernel<<<dim3(4, 8, 32), 256, ATTN_SMEM>>>(
        proj, 1280, 512, PSTRIDE,
        proj, 1280, 768, PSTRIDE,
        proj, 1280, 1024, PSTRIDE,
        wimg, MSTRIDE,
        ctx, CSTRIDE);

    // 6. out-proj for both modalities -> attended_*
    gemm_tc<<<dim3(128, 2, 1), 256>>>(ctx, ctx, 256, wot, 256, 0, out_b, 0,
                                      att_img, 256, 0, 0);

    // 7. consistency
    gemm_tc<<<dim3(128, 2, 1), 256>>>(att_img, att_img, 256, cw1, 256, 0, cb1, 0,
                                      Hbuf, 256, 0, 1);
    cons_reduce<<<2048, 256>>>(Hbuf, cw2, cb2, cons);

    // 8. cross-modal
    gemm_tc<<<dim3(64, 2, 1), 256>>>(att_img, att_img, 256, wcat, 1280, 512, bias1, 512,
                                     qc, 256, 0, 0);
    gemm_tc<<<dim3(64, 4, 1), 256>>>(att_txt, att_txt, 256, wcat, 1280, 768, bias1, 768,
                                     kvc, 512, 0, 0);
    attn_kernel<<<dim3(4, 8, 16), 256, ATTN_SMEM>>>(
        qc, 256, 0, 0,
        kvc, 512, 0, 0,
        kvc, 512, 256, 0,
        nullptr, 0,
        ctx2, 0);
    gemm_tc<<<dim3(64, 2, 1), 256>>>(ctx2, ctx2, 256, wot, 256, 0, out_b, 0,
                                     cross, 256, 0, 0);
}

// round 5
// speedup vs baseline: 2.7051x; 1.1321x over previous
#include <cuda_runtime.h>
#include <cuda_bf16.h>
#include <cstddef>
#include <cstdint>

// Problem constants: B=16, N=512, D=256, H=8, DH=32, E=16384
// d_out layout (floats):
//   attended_img   [0,        2097152)
//   attended_text  [2097152,  4194304)
//   cross_modal    [4194304,  6291456)
//   img_weights    [6291456, 10485760)
//   text_weights   [10485760,14680064)
//   img_cons       [14680064,14688256)
//   text_cons      [14688256,14696448)

#define OFF_WCAT   0u             // 256*1280
#define OFF_BIAS1  327680u        // 1280
#define OFF_WOT    328960u        // 256*256
#define OFF_PROJ   394496u        // 16384*1280  (reused as H for consistency)
#define OFF_CTX    21366016u      // 16384*256
#define OFF_QC     25560320u      // 8192*256
#define OFF_KVC    27657472u      // 8192*512
#define OFF_CTX2   31851776u      // 8192*256
#define SCRATCH_FLOATS 33948928u

__device__ float g_scratch[SCRATCH_FLOATS];

// ---------------------------------------------------------------------------
__device__ __forceinline__ uint32_t f2tf32(float f) {
    uint32_t r;
    asm("cvt.rna.tf32.f32 %0, %1;" : "=r"(r) : "f"(f));
    return r;
}

__device__ __forceinline__ void mma_tf32(float& d0, float& d1, float& d2, float& d3,
                                         uint32_t a0, uint32_t a1, uint32_t a2, uint32_t a3,
                                         uint32_t b0, uint32_t b1)
{
    asm volatile(
        "mma.sync.aligned.m16n8k8.row.col.f32.tf32.tf32.f32 "
        "{%0,%1,%2,%3}, {%4,%5,%6,%7}, {%8,%9}, {%0,%1,%2,%3};"
        : "+f"(d0), "+f"(d1), "+f"(d2), "+f"(d3)
        : "r"(a0), "r"(a1), "r"(a2), "r"(a3), "r"(b0), "r"(b1));
}

// ---------------------------------------------------------------------------
// Pack: wcat[k][c] (256 x 1280), bias1[1280], wot = out_w^T (256x256)
// ---------------------------------------------------------------------------
__global__ void pack_kernel(const float* __restrict__ w1, const float* __restrict__ b1,
                            const float* __restrict__ in_w, const float* __restrict__ in_b,
                            const float* __restrict__ out_w,
                            float* __restrict__ wcat, float* __restrict__ bias1,
                            float* __restrict__ wot)
{
    int idx = blockIdx.x * 256 + threadIdx.x;
    if (idx < 327680) {
        int k = idx / 1280, c = idx % 1280;
        float v;
        if (c < 256)       v = w1[k * 256 + c];
        else if (c < 512)  v = w1[(256 + k) * 256 + (c - 256)];
        else if (c < 768)  v = in_w[(c - 512) * 256 + k];
        else if (c < 1024) v = in_w[(c - 768 + 256) * 256 + k];
        else               v = in_w[(c - 1024 + 512) * 256 + k];
        wcat[idx] = v;
    } else if (idx < 328960) {
        int c = idx - 327680;
        float v = (c < 256) ? b1[c] : (c < 512 ? 0.0f : in_b[c - 512]);
        bias1[c] = v;
    } else if (idx < 394496) {
        int i = idx - 328960;
        int k = i / 256, n = i % 256;
        wot[i] = out_w[n * 256 + k];
    }
}

// ---------------------------------------------------------------------------
// Tensor-core tf32 GEMM with register-prefetch double buffering.
// ---------------------------------------------------------------------------
__global__ void gemm_tc(const float* __restrict__ X0, const float* __restrict__ X1,
                        int ldx,
                        const float* __restrict__ W, int ldw, int woff,
                        const float* __restrict__ bias, int boff,
                        float* __restrict__ C, int ldc, size_t czstride, int relu)
{
    __shared__ uint32_t As[128][36];
    __shared__ uint32_t Bs[32][136];

    int z = blockIdx.z;
    const float* X = z ? X1 : X0;
    float* Cz = C + (size_t)z * czstride;

    int t = threadIdx.x;
    int lane = t & 31, w = t >> 5;
    int gid = lane >> 2, tig = lane & 3;
    int wm = w >> 2, wn = w & 3;
    int m0 = blockIdx.x * 128, n0 = blockIdx.y * 128;

    int ar[4], ac[4], br4[4], bc4[4];
    #pragma unroll
    for (int i = 0; i < 4; i++) {
        int lin = i * 1024 + t * 4;
        ar[i] = lin >> 5;  ac[i]  = lin & 31;
        br4[i] = lin >> 7; bc4[i] = lin & 127;
    }

    float acc[4][4][4];
    #pragma unroll
    for (int mi = 0; mi < 4; mi++)
        #pragma unroll
        for (int ni = 0; ni < 4; ni++)
            #pragma unroll
            for (int q = 0; q < 4; q++) acc[mi][ni][q] = 0.0f;

    float4 xa[4], wb[4];
    #pragma unroll
    for (int i = 0; i < 4; i++) {
        xa[i] = *(const float4*)(X + (size_t)(m0 + ar[i]) * ldx + ac[i]);
        wb[i] = *(const float4*)(W + (size_t)br4[i] * ldw + woff + n0 + bc4[i]);
    }

    for (int ch = 0; ch < 8; ch++) {
        #pragma unroll
        for (int i = 0; i < 4; i++) {
            As[ar[i]][ac[i] + 0] = f2tf32(xa[i].x);
            As[ar[i]][ac[i] + 1] = f2tf32(xa[i].y);
            As[ar[i]][ac[i] + 2] = f2tf32(xa[i].z);
            As[ar[i]][ac[i] + 3] = f2tf32(xa[i].w);
            Bs[br4[i]][bc4[i] + 0] = f2tf32(wb[i].x);
            Bs[br4[i]][bc4[i] + 1] = f2tf32(wb[i].y);
            Bs[br4[i]][bc4[i] + 2] = f2tf32(wb[i].z);
            Bs[br4[i]][bc4[i] + 3] = f2tf32(wb[i].w);
        }
        __syncthreads();

        if (ch < 7) {
            int k0 = (ch + 1) * 32;
            #pragma unroll
            for (int i = 0; i < 4; i++) {
                xa[i] = *(const float4*)(X + (size_t)(m0 + ar[i]) * ldx + k0 + ac[i]);
                wb[i] = *(const float4*)(W + (size_t)(k0 + br4[i]) * ldw + woff + n0 + bc4[i]);
            }
        }

        #pragma unroll
        for (int ks = 0; ks < 4; ks++) {
            int kk = ks * 8;
            uint32_t a[4][4], b[4][2];
            #pragma unroll
            for (int mi = 0; mi < 4; mi++) {
                int rb = wm * 64 + mi * 16 + gid;
                a[mi][0] = As[rb][kk + tig];
                a[mi][1] = As[rb + 8][kk + tig];
                a[mi][2] = As[rb][kk + tig + 4];
                a[mi][3] = As[rb + 8][kk + tig + 4];
            }
            #pragma unroll
            for (int ni = 0; ni < 4; ni++) {
                int cb = wn * 32 + ni * 8 + gid;
                b[ni][0] = Bs[kk + tig][cb];
                b[ni][1] = Bs[kk + tig + 4][cb];
            }
            #pragma unroll
            for (int mi = 0; mi < 4; mi++)
                #pragma unroll
                for (int ni = 0; ni < 4; ni++)
                    mma_tf32(acc[mi][ni][0], acc[mi][ni][1], acc[mi][ni][2], acc[mi][ni][3],
                             a[mi][0], a[mi][1], a[mi][2], a[mi][3],
                             b[ni][0], b[ni][1]);
        }
        __syncthreads();
    }

    #pragma unroll
    for (int mi = 0; mi < 4; mi++) {
        int r0 = m0 + wm * 64 + mi * 16 + gid;
        #pragma unroll
        for (int ni = 0; ni < 4; ni++) {
            int col = n0 + wn * 32 + ni * 8 + 2 * tig;
            float bb0 = bias ? bias[boff + col]     : 0.0f;
            float bb1 = bias ? bias[boff + col + 1] : 0.0f;
            float2 v0, v1;
            v0.x = acc[mi][ni][0] + bb0; v0.y = acc[mi][ni][1] + bb1;
            v1.x = acc[mi][ni][2] + bb0; v1.y = acc[mi][ni][3] + bb1;
            if (relu) {
                v0.x = fmaxf(v0.x, 0.0f); v0.y = fmaxf(v0.y, 0.0f);
                v1.x = fmaxf(v1.x, 0.0f); v1.y = fmaxf(v1.y, 0.0f);
            }
            *(float2*)(Cz + (size_t)r0 * ldc + col)       = v0;
            *(float2*)(Cz + (size_t)(r0 + 8) * ldc + col) = v1;
        }
    }
}

// ---------------------------------------------------------------------------
// Edge scatter: one warp per (modality, batch, edge).
// ---------------------------------------------------------------------------
__global__ void edge_kernel(const float* __restrict__ proj,
                            const int* __restrict__ src, const int* __restrict__ dst,
                            const float* __restrict__ w2, const float* __restrict__ b2p,
                            float* __restrict__ wout)
{
    int gw   = (blockIdx.x * blockDim.x + threadIdx.x) >> 5;
    int lane = threadIdx.x & 31;
    int e = gw & 16383;
    int b = (gw >> 14) & 15;
    int m = gw >> 18;
    int s = src[e], d = dst[e];

    const float4* ar = (const float4*)(proj + ((size_t)m * 8192 + b * 512 + s) * 1280);
    const float4* br = (const float4*)(proj + ((size_t)m * 8192 + b * 512 + d) * 1280 + 256);
    const float4* w4 = (const float4*)w2;

    float p = 0.0f;
    #pragma unroll
    for (int u = 0; u < 2; u++) {
        int idx = u * 32 + lane;
        float4 a = ar[idx], bb = br[idx], w = w4[idx];
        p += fmaxf(a.x + bb.x, 0.0f) * w.x;
        p += fmaxf(a.y + bb.y, 0.0f) * w.y;
        p += fmaxf(a.z + bb.z, 0.0f) * w.z;
        p += fmaxf(a.w + bb.w, 0.0f) * w.w;
    }
    #pragma unroll
    for (int off = 16; off > 0; off >>= 1)
        p += __shfl_xor_sync(0xFFFFFFFFu, p, off);
    if (lane == 0) {
        float v = 1.0f / (1.0f + __expf(-(p + b2p[0])));
        wout[(size_t)m * 4194304 + (size_t)b * 262144 + (size_t)s * 512 + d] = v;
    }
}

// ---------------------------------------------------------------------------
// Tensor-core attention, 512 threads / 16 warps per block (256 query rows).
// grid = (2 chunks, 8 heads, Z); z -> (b = z&15, mz = z>>4).
// Smem: K/V 38912 words + 16 warps x 1088 words P = 56320 words = 225280 B.
// __launch_bounds__(512,1): 128 regs/thread, 512x128 = full RF.
// ---------------------------------------------------------------------------
__global__ __launch_bounds__(512, 1)
void attn_kernel(const float* __restrict__ qbuf, int qld, int qoff, size_t qzs,
                 const float* __restrict__ kbuf, int kld, int koff, size_t kzs,
                 const float* __restrict__ vbuf, int vld, int voff, size_t vzs,
                 const float* __restrict__ mask, size_t mzs,
                 float* __restrict__ ctx, size_t czs)
{
    extern __shared__ uint32_t sm[];
    uint32_t* Ks = sm;               // [512][36]
    uint32_t* Vs = sm + 18432;       // [512][40]
    uint32_t* Pw = sm + 38912;       // 16 warps x [16][68]

    int zb = blockIdx.z;
    int b = zb & 15, mz = zb >> 4;
    const float* Q = qbuf + (size_t)mz * qzs;
    const float* K = kbuf + (size_t)mz * kzs;
    const float* V = vbuf + (size_t)mz * vzs;
    const float* M = mask ? mask + (size_t)mz * mzs : nullptr;
    float* O = ctx + (size_t)mz * czs;

    int h = blockIdx.y, chunk = blockIdx.x;
    int t = threadIdx.x, lane = t & 31, w = t >> 5;
    int gid = lane >> 2, tig = lane & 3;

    for (int i = t; i < 4096; i += 512) {
        int row = i >> 3, c4 = (i & 7) * 4;
        size_t rk = (size_t)(b * 512 + row);
        float4 kv = *(const float4*)(K + rk * kld + koff + h * 32 + c4);
        uint4 kt; kt.x = f2tf32(kv.x); kt.y = f2tf32(kv.y); kt.z = f2tf32(kv.z); kt.w = f2tf32(kv.w);
        *(uint4*)&Ks[row * 36 + c4] = kt;
        float4 vv = *(const float4*)(V + rk * vld + voff + h * 32 + c4);
        uint4 vt; vt.x = f2tf32(vv.x); vt.y = f2tf32(vv.y); vt.z = f2tf32(vv.z); vt.w = f2tf32(vv.w);
        *(uint4*)&Vs[row * 40 + c4] = vt;
    }
    __syncthreads();

    uint32_t* Ps = Pw + w * 1088;
    int i0 = chunk * 256 + w * 16;
    const float scale = 0.17677669529663687f;  // 1/sqrt(32)

    uint32_t qa[4][4];
    {
        const float* q0p = Q + (size_t)(b * 512 + i0 + gid) * qld + qoff + h * 32;
        const float* q1p = q0p + (size_t)8 * qld;
        #pragma unroll
        for (int ks = 0; ks < 4; ks++) {
            qa[ks][0] = f2tf32(q0p[ks * 8 + tig] * scale);
            qa[ks][1] = f2tf32(q1p[ks * 8 + tig] * scale);
            qa[ks][2] = f2tf32(q0p[ks * 8 + tig + 4] * scale);
            qa[ks][3] = f2tf32(q1p[ks * 8 + tig + 4] * scale);
        }
    }

    const float* mrow0 = M ? M + (size_t)b * 262144 + (size_t)(i0 + gid) * 512 : nullptr;
    const float* mrow1 = mrow0 ? mrow0 + 8 * 512 : nullptr;

    float oacc[4][4];
    #pragma unroll
    for (int vt = 0; vt < 4; vt++)
        #pragma unroll
        for (int q = 0; q < 4; q++) oacc[vt][q] = 0.0f;
    float rsum0 = 0.0f, rsum1 = 0.0f;

    for (int kc = 0; kc < 8; kc++) {
        float2 mv0[8], mv1[8];
        if (mrow0) {
            #pragma unroll
            for (int nt = 0; nt < 8; nt++) {
                int col = kc * 64 + nt * 8 + 2 * tig;
                mv0[nt] = *(const float2*)(mrow0 + col);
                mv1[nt] = *(const float2*)(mrow1 + col);
            }
        }

        float sacc[8][4];
        #pragma unroll
        for (int nt = 0; nt < 8; nt++)
            #pragma unroll
            for (int q = 0; q < 4; q++) sacc[nt][q] = 0.0f;

        #pragma unroll
        for (int ks = 0; ks < 4; ks++) {
            #pragma unroll
            for (int nt = 0; nt < 8; nt++) {
                int key = kc * 64 + nt * 8 + gid;
                uint32_t b0 = Ks[key * 36 + ks * 8 + tig];
                uint32_t b1 = Ks[key * 36 + ks * 8 + tig + 4];
                mma_tf32(sacc[nt][0], sacc[nt][1], sacc[nt][2], sacc[nt][3],
                         qa[ks][0], qa[ks][1], qa[ks][2], qa[ks][3], b0, b1);
            }
        }

        #pragma unroll
        for (int nt = 0; nt < 8; nt++) {
            float s0 = sacc[nt][0], s1 = sacc[nt][1];
            float s2 = sacc[nt][2], s3 = sacc[nt][3];
            if (mrow0) {
                s0 += mv0[nt].x; s1 += mv0[nt].y;
                s2 += mv1[nt].x; s3 += mv1[nt].y;
            }
            float p0 = __expf(s0), p1 = __expf(s1);
            float p2 = __expf(s2), p3 = __expf(s3);
            rsum0 += p0 + p1;
            rsum1 += p2 + p3;
            uint2 u0; u0.x = f2tf32(p0); u0.y = f2tf32(p1);
            uint2 u1; u1.x = f2tf32(p2); u1.y = f2tf32(p3);
            *(uint2*)&Ps[gid * 68 + nt * 8 + 2 * tig]       = u0;
            *(uint2*)&Ps[(gid + 8) * 68 + nt * 8 + 2 * tig] = u1;
        }
        __syncwarp();

        #pragma unroll
        for (int ks2 = 0; ks2 < 8; ks2++) {
            uint32_t a0 = Ps[gid * 68 + ks2 * 8 + tig];
            uint32_t a1 = Ps[(gid + 8) * 68 + ks2 * 8 + tig];
            uint32_t a2 = Ps[gid * 68 + ks2 * 8 + tig + 4];
            uint32_t a3 = Ps[(gid + 8) * 68 + ks2 * 8 + tig + 4];
            int keyb = kc * 64 + ks2 * 8;
            #pragma unroll
            for (int vt = 0; vt < 4; vt++) {
                uint32_t b0 = Vs[(keyb + tig) * 40 + vt * 8 + gid];
                uint32_t b1 = Vs[(keyb + tig + 4) * 40 + vt * 8 + gid];
                mma_tf32(oacc[vt][0], oacc[vt][1], oacc[vt][2], oacc[vt][3],
                         a0, a1, a2, a3, b0, b1);
            }
        }
        __syncwarp();
    }

    rsum0 += __shfl_xor_sync(0xFFFFFFFFu, rsum0, 1);
    rsum0 += __shfl_xor_sync(0xFFFFFFFFu, rsum0, 2);
    rsum1 += __shfl_xor_sync(0xFFFFFFFFu, rsum1, 1);
    rsum1 += __shfl_xor_sync(0xFFFFFFFFu, rsum1, 2);
    float inv0 = 1.0f / rsum0, inv1 = 1.0f / rsum1;

    size_t r0 = (size_t)(b * 512 + i0 + gid) * 256 + h * 32;
    size_t r1 = r0 + (size_t)8 * 256;
    #pragma unroll
    for (int vt = 0; vt < 4; vt++) {
        float2 v0; v0.x = oacc[vt][0] * inv0; v0.y = oacc[vt][1] * inv0;
        float2 v1; v1.x = oacc[vt][2] * inv1; v1.y = oacc[vt][3] * inv1;
        *(float2*)(O + r0 + vt * 8 + 2 * tig) = v0;
        *(float2*)(O + r1 + vt * 8 + 2 * tig) = v1;
    }
}

// ---------------------------------------------------------------------------
__global__ void cons_reduce(const float* __restrict__ H, const float* __restrict__ cw2,
                            const float* __restrict__ cb2, float* __restrict__ out)
{
    int gw   = (blockIdx.x * blockDim.x + threadIdx.x) >> 5;
    int lane = threadIdx.x & 31;
    const float4* h4 = (const float4*)(H + (size_t)gw * 256);
    const float4* w4 = (const float4*)cw2;
    float p = 0.0f;
    #pragma unroll
    for (int u = 0; u < 2; u++) {
        int idx = u * 32 + lane;
        float4 a = h4[idx], w = w4[idx];
        p += a.x * w.x + a.y * w.y + a.z * w.z + a.w * w.w;
    }
    #pragma unroll
    for (int off = 16; off > 0; off >>= 1)
        p += __shfl_xor_sync(0xFFFFFFFFu, p, off);
    if (lane == 0)
        out[gw] = 1.0f / (1.0f + __expf(-(p + cb2[0])));
}

// ---------------------------------------------------------------------------
extern "C" void kernel_launch(void* const* d_in, const int* in_sizes, int n_in,
                              void* d_out, int out_size)
{
    const float* img   = (const float*)d_in[0];
    const float* txt   = (const float*)d_in[1];
    const int*   src   = (const int*)  d_in[2];
    const int*   dst   = (const int*)  d_in[3];
    const float* w1    = (const float*)d_in[4];
    const float* b1    = (const float*)d_in[5];
    const float* w2    = (const float*)d_in[6];
    const float* b2    = (const float*)d_in[7];
    const float* in_w  = (const float*)d_in[8];
    const float* in_b  = (const float*)d_in[9];
    const float* out_w = (const float*)d_in[10];
    const float* out_b = (const float*)d_in[11];
    const float* cw1   = (const float*)d_in[12];
    const float* cb1   = (const float*)d_in[13];
    const float* cw2   = (const float*)d_in[14];
    const float* cb2   = (const float*)d_in[15];
    float* out = (float*)d_out;

    float* S = nullptr;
    cudaGetSymbolAddress((void**)&S, g_scratch);

    float* wcat  = S + OFF_WCAT;
    float* bias1 = S + OFF_BIAS1;
    float* wot   = S + OFF_WOT;
    float* proj  = S + OFF_PROJ;
    float* ctx   = S + OFF_CTX;
    float* qc    = S + OFF_QC;
    float* kvc   = S + OFF_KVC;
    float* ctx2  = S + OFF_CTX2;
    float* Hbuf  = proj;

    float* att_img = out;
    float* att_txt = out + 2097152;
    float* cross   = out + 4194304;
    float* wimg    = out + 6291456;
    float* cons    = out + 14680064;

    const int ATTN_SMEM = 225280;
    cudaFuncSetAttribute(attn_kernel, cudaFuncAttributeMaxDynamicSharedMemorySize, ATTN_SMEM);

    const size_t PSTRIDE = (size_t)8192 * 1280;
    const size_t CSTRIDE = (size_t)8192 * 256;
    const size_t MSTRIDE = (size_t)4194304;

    // 1. pack fused weights
    pack_kernel<<<1541, 256>>>(w1, b1, in_w, in_b, out_w, wcat, bias1, wot);

    // 2. zero both weight matrices
    cudaMemsetAsync(wimg, 0, (size_t)8388608 * 4);

    // 3. fused node projections (both modalities, grid.z=2)
    gemm_tc<<<dim3(64, 10, 2), 256>>>(img, txt, 256, wcat, 1280, 0, bias1, 0,
                                      proj, 1280, PSTRIDE, 0);

    // 4. per-edge causal weights (both modalities)
    edge_kernel<<<65536, 256>>>(proj, src, dst, w2, b2, wimg);

    // 5. masked self-attention, both modalities (grid.z=32, 512-thread blocks)
    attn_kernel<<<dim3(2, 8, 32), 512, ATTN_SMEM>>>(
        proj, 1280, 512, PSTRIDE,
        proj, 1280, 768, PSTRIDE,
        proj, 1280, 1024, PSTRIDE,
        wimg, MSTRIDE,
        ctx, CSTRIDE);

    // 6. out-proj for both modalities -> attended_*
    gemm_tc<<<dim3(128, 2, 1), 256>>>(ctx, ctx, 256, wot, 256, 0, out_b, 0,
                                      att_img, 256, 0, 0);

    // 7. consistency
    gemm_tc<<<dim3(128, 2, 1), 256>>>(att_img, att_img, 256, cw1, 256, 0, cb1, 0,
                                      Hbuf, 256, 0, 1);
    cons_reduce<<<2048, 256>>>(Hbuf, cw2, cb2, cons);

    // 8. cross-modal
    gemm_tc<<<dim3(64, 2, 1), 256>>>(att_img, att_img, 256, wcat, 1280, 512, bias1, 512,
                                     qc, 256, 0, 0);
    gemm_tc<<<dim3(64, 4, 1), 256>>>(att_txt, att_txt, 256, wcat, 1280, 768, bias1, 768,
                                     kvc, 512, 0, 0);
    attn_kernel<<<dim3(2, 8, 16), 512, ATTN_SMEM>>>(
        qc, 256, 0, 0,
        kvc, 512, 0, 0,
        kvc, 512, 256, 0,
        nullptr, 0,
        ctx2, 0);
    gemm_tc<<<dim3(64, 2, 1), 256>>>(ctx2, ctx2, 256, wot, 256, 0, out_b, 0,
                                     cross, 256, 0, 0);
}